// round 3
// baseline (speedup 1.0000x reference)
#include <cuda_runtime.h>
#include <cuda_bf16.h>
#include <math.h>

#define NROWS 131072
#define RB128 (NROWS/128)   // 1024
#define MARGIN 1.0f
#define CAND_CAP 32

// ---------------- scratch (device globals; no allocation allowed) ----------------
__device__ float g_z   [(size_t)NROWS * 256];
__device__ float g_res [(size_t)NROWS * 256];
__device__ float g_q1  [(size_t)NROWS * 256];
__device__ __nv_bfloat16 g_qbf [(size_t)NROWS * 256];
__device__ __nv_bfloat16 g_dbA [(size_t)NROWS * 512];
__device__ __nv_bfloat16 g_dbB [(size_t)NROWS * 512];
// split-precision encoder buffers (3 bf16 planes, plane-blocked along K)
__device__ __nv_bfloat16 g_spin[(size_t)NROWS * 192];    // state split, Kp=64 (padded from 56)
__device__ __nv_bfloat16 g_sp1 [(size_t)NROWS * 1536];   // h1 split, Kp=512
__device__ __nv_bfloat16 g_sp2 [(size_t)NROWS * 1536];   // h2 split, Kp=512
__device__ __nv_bfloat16 g_wsp1[512 * 192];
__device__ __nv_bfloat16 g_wsp2[512 * 1536];
__device__ __nv_bfloat16 g_wsp3[256 * 1536];
// decoder bf16 weights (transposed, single plane)
__device__ __nv_bfloat16 g_wt1[512 * 256];
__device__ __nv_bfloat16 g_wt2[512 * 512];
__device__ __nv_bfloat16 g_wt3[56 * 512];
__device__ __nv_bfloat16 g_cbh[2 * 1024 * 256];
__device__ float g_cn  [2 * 1024];
__device__ float g_l1p [RB128];
__device__ float g_vqp [RB128];

// ---------------- small helpers ----------------
__device__ __forceinline__ unsigned smaddr(const void* p) {
    return (unsigned)__cvta_generic_to_shared(p);
}
__device__ __forceinline__ void cpa16(unsigned dst, const void* src, int sz) {
    asm volatile("cp.async.cg.shared.global [%0], [%1], 16, %2;\n"
                 :: "r"(dst), "l"(src), "r"(sz));
}
#define CP_COMMIT asm volatile("cp.async.commit_group;\n")
template<int N> __device__ __forceinline__ void cp_wait() {
    asm volatile("cp.async.wait_group %0;\n" :: "n"(N));
}
__device__ __forceinline__ void mma_bf16(float* c, const unsigned* a, unsigned b0, unsigned b1) {
    asm volatile(
        "mma.sync.aligned.m16n8k16.row.col.f32.bf16.bf16.f32 "
        "{%0,%1,%2,%3}, {%4,%5,%6,%7}, {%8,%9}, {%0,%1,%2,%3};\n"
        : "+f"(c[0]), "+f"(c[1]), "+f"(c[2]), "+f"(c[3])
        : "r"(a[0]), "r"(a[1]), "r"(a[2]), "r"(a[3]), "r"(b0), "r"(b1));
}
__device__ __forceinline__ unsigned fford(float f) {
    unsigned u = __float_as_uint(f);
    return (u & 0x80000000u) ? ~u : (u | 0x80000000u);
}
__device__ __forceinline__ float iford(unsigned u) {
    return __uint_as_float((u & 0x80000000u) ? (u ^ 0x80000000u) : ~u);
}
// exact 3-way bf16 decomposition (v == b0+b1+b2 to ~26 bits)
__device__ __forceinline__ void split3(float v, __nv_bfloat16& b0, __nv_bfloat16& b1, __nv_bfloat16& b2)
{
    b0 = __float2bfloat16(v);
    float r = v - __bfloat162float(b0);
    b1 = __float2bfloat16(r);
    float r2 = r - __bfloat162float(b1);
    b2 = __float2bfloat16(r2);
}

// ================= prep kernels =================
__global__ __launch_bounds__(256) void cn_k(const float* __restrict__ cb, float* __restrict__ cn)
{
    int w = (blockIdx.x * blockDim.x + threadIdx.x) >> 5;
    int lane = threadIdx.x & 31;
    if (w < 2048) {
        const float* c = cb + (size_t)w * 256;
        float s = 0.f;
        #pragma unroll
        for (int k = lane; k < 256; k += 32) s = fmaf(c[k], c[k], s);
        #pragma unroll
        for (int off = 16; off > 0; off >>= 1) s += __shfl_xor_sync(0xffffffff, s, off);
        if (lane == 0) cn[w] = 0.5f * s;
    }
}
__global__ __launch_bounds__(256) void cvt_k(const float* __restrict__ src,
                                             __nv_bfloat16* __restrict__ dst, int n)
{
    int i = blockIdx.x * 256 + threadIdx.x;
    if (i < n) dst[i] = __float2bfloat16(src[i]);
}
// W [K][M] fp32 -> BT [M][K] bf16 (decoder, single plane)
__global__ __launch_bounds__(256) void tr_k(const float* __restrict__ W,
                                            __nv_bfloat16* __restrict__ BT, int K, int M)
{
    int i = blockIdx.x * 256 + threadIdx.x;
    if (i < K * M) {
        int k = i / M, m = i % M;
        BT[(size_t)m * K + k] = __float2bfloat16(W[i]);
    }
}
// state [N][56] fp32 -> [N][3*64] bf16 plane-blocked (zero-padded k 56..63)
__global__ __launch_bounds__(256) void split_state_k(const float* __restrict__ S,
                                                     __nv_bfloat16* __restrict__ D)
{
    long i = (long)blockIdx.x * 256 + threadIdx.x;   // over N*64
    if (i < (long)NROWS * 64) {
        long n = i >> 6; int k = (int)(i & 63);
        float v = (k < 56) ? S[n * 56 + k] : 0.f;
        __nv_bfloat16 b0, b1, b2;
        split3(v, b0, b1, b2);
        __nv_bfloat16* d = D + n * 192;
        d[k] = b0; d[64 + k] = b1; d[128 + k] = b2;
    }
}
// W [K][M] fp32 -> BT [M][3*Kp] bf16 plane-blocked transposed (zero-pad k>=K)
__global__ __launch_bounds__(256) void split_w_k(const float* __restrict__ W,
                                                 __nv_bfloat16* __restrict__ BT,
                                                 int K, int M, int Kp)
{
    long i = (long)blockIdx.x * 256 + threadIdx.x;   // over M*Kp
    if (i < (long)M * Kp) {
        int m = (int)(i / Kp), k = (int)(i % Kp);
        float v = (k < K) ? W[(size_t)k * M + m] : 0.f;
        __nv_bfloat16 b0, b1, b2;
        split3(v, b0, b1, b2);
        __nv_bfloat16* d = BT + (size_t)m * 3 * Kp;
        d[k] = b0; d[Kp + k] = b1; d[2 * Kp + k] = b2;
    }
}

// ================= split-precision bf16 HMMA GEMM (encoder) =================
// C[rows,M] ~= fp32( A[rows,Kp]_split3 @ B[M,Kp]_split3^T ) + bias
// A layout [rows][3*Kp], BT layout [M][3*Kp], plane-blocked.
// 6 plane pairs, smallest-magnitude first: (2,0)(1,1)(0,2)(0,1)(1,0)(0,0).
// F32OUT=1: write fp32 (no relu). F32OUT=0: relu + split3 -> C planes [rows][3*KpN].
__constant__ int c_PI[6] = {2, 1, 0, 0, 1, 0};
__constant__ int c_PJ[6] = {0, 1, 2, 1, 0, 0};

template<int F32OUT>
__global__ __launch_bounds__(256) void shgemm_k(
    const __nv_bfloat16* __restrict__ A, const __nv_bfloat16* __restrict__ BT,
    const float* __restrict__ bias, void* __restrict__ Cv,
    int Kp, int M, int KpN)
{
    extern __shared__ __align__(16) char sm[];
    __nv_bfloat16* As = (__nv_bfloat16*)sm;            // [2][128][72]
    __nv_bfloat16* Bs = As + 2 * 128 * 72;

    const int tid = threadIdx.x;
    const int lane = tid & 31, wid = tid >> 5;
    const int wm = wid & 3, wn = wid >> 2;
    const int row0 = blockIdx.x * 128;
    const int col0 = blockIdx.y * 128;
    const unsigned As0 = smaddr(As), Bs0 = smaddr(Bs);
    const int lda = 3 * Kp;
    const int nkc = Kp >> 6;
    const int nch = 6 * nkc;

    float acc[2][8][4];
    #pragma unroll
    for (int a = 0; a < 2; a++)
        #pragma unroll
        for (int b = 0; b < 8; b++)
            #pragma unroll
            for (int c = 0; c < 4; c++) acc[a][b][c] = 0.f;

    auto fill = [&](int stage, int c) {
        int pr = c / nkc, kc = c % nkc;
        int aoff = c_PI[pr] * Kp + kc * 64;
        int boff = c_PJ[pr] * Kp + kc * 64;
        #pragma unroll
        for (int i = 0; i < 4; i++) {
            int ch = tid + 256 * i;
            int r = ch >> 3, g = ch & 7;
            cpa16(As0 + (unsigned)(stage * 9216 + r * 72 + g * 8) * 2,
                  A + (size_t)(row0 + r) * lda + aoff + g * 8, 16);
        }
        #pragma unroll
        for (int i = 0; i < 4; i++) {
            int ch = tid + 256 * i;
            int r = ch >> 3, g = ch & 7;
            cpa16(Bs0 + (unsigned)(stage * 9216 + r * 72 + g * 8) * 2,
                  BT + (size_t)(col0 + r) * lda + boff + g * 8, 16);
        }
    };

    const int g = lane >> 2, q2 = (lane & 3) * 2;

    fill(0, 0);
    CP_COMMIT;
    for (int c = 0; c < nch; c++) {
        if (c + 1 < nch) {
            fill((c + 1) & 1, c + 1);
            CP_COMMIT;
            cp_wait<1>();
        } else {
            cp_wait<0>();
        }
        __syncthreads();
        int stage = c & 1;
        #pragma unroll
        for (int kk = 0; kk < 64; kk += 16) {
            unsigned a[2][4];
            #pragma unroll
            for (int mf = 0; mf < 2; mf++) {
                const __nv_bfloat16* p = As + stage * 9216 + (wm * 32 + mf * 16 + g) * 72;
                a[mf][0] = *(const unsigned*)(p + kk + q2);
                a[mf][1] = *(const unsigned*)(p + 8 * 72 + kk + q2);
                a[mf][2] = *(const unsigned*)(p + kk + 8 + q2);
                a[mf][3] = *(const unsigned*)(p + 8 * 72 + kk + 8 + q2);
            }
            #pragma unroll
            for (int nf = 0; nf < 8; nf++) {
                const __nv_bfloat16* bp = Bs + stage * 9216 + (wn * 64 + nf * 8 + g) * 72 + kk + q2;
                unsigned b0 = *(const unsigned*)bp;
                unsigned b1 = *(const unsigned*)(bp + 8);
                mma_bf16(acc[0][nf], a[0], b0, b1);
                mma_bf16(acc[1][nf], a[1], b0, b1);
            }
        }
        __syncthreads();
    }

    if (F32OUT) {
        float* C = (float*)Cv;
        #pragma unroll
        for (int mf = 0; mf < 2; mf++) {
            int r1 = row0 + wm * 32 + mf * 16 + g;
            #pragma unroll
            for (int nf = 0; nf < 8; nf++) {
                int cc = col0 + wn * 64 + nf * 8 + q2;
                float2 o0 = make_float2(acc[mf][nf][0] + bias[cc], acc[mf][nf][1] + bias[cc + 1]);
                float2 o1 = make_float2(acc[mf][nf][2] + bias[cc], acc[mf][nf][3] + bias[cc + 1]);
                *(float2*)(C + (size_t)r1 * M + cc) = o0;
                *(float2*)(C + (size_t)(r1 + 8) * M + cc) = o1;
            }
        }
    } else {
        __nv_bfloat16* C = (__nv_bfloat16*)Cv;
        const size_t strd = 3 * (size_t)KpN;
        #pragma unroll
        for (int mf = 0; mf < 2; mf++) {
            int r1 = row0 + wm * 32 + mf * 16 + g;
            #pragma unroll
            for (int nf = 0; nf < 8; nf++) {
                int cc = col0 + wn * 64 + nf * 8 + q2;
                #pragma unroll
                for (int half = 0; half < 2; half++) {
                    int r = r1 + (half ? 8 : 0);
                    float v0 = fmaxf(acc[mf][nf][2 * half + 0] + bias[cc], 0.f);
                    float v1 = fmaxf(acc[mf][nf][2 * half + 1] + bias[cc + 1], 0.f);
                    __nv_bfloat16 a0, a1, a2, b0, b1, b2;
                    split3(v0, a0, a1, a2);
                    split3(v1, b0, b1, b2);
                    __nv_bfloat16* base = C + (size_t)r * strd + cc;
                    __nv_bfloat162 p0; p0.x = a0; p0.y = b0;
                    __nv_bfloat162 p1; p1.x = a1; p1.y = b1;
                    __nv_bfloat162 p2; p2.x = a2; p2.y = b2;
                    *(__nv_bfloat162*)(base)            = p0;
                    *(__nv_bfloat162*)(base + KpN)      = p1;
                    *(__nv_bfloat162*)(base + 2 * KpN)  = p2;
                }
            }
        }
    }
}

// ================= bf16 HGEMM (decoder, unchanged from round 2) =================
__device__ __forceinline__ void hfill(const __nv_bfloat16* __restrict__ A,
                                      const __nv_bfloat16* __restrict__ BT,
                                      unsigned As0, unsigned Bs0, int stage, int k0,
                                      int row0, int col0, int K, int M, int tid)
{
    #pragma unroll
    for (int i = 0; i < 4; i++) {
        int ch = tid + 256 * i;
        int r = ch >> 3, g = ch & 7;
        cpa16(As0 + (unsigned)(stage * 9216 + r * 72 + g * 8) * 2,
              A + (size_t)(row0 + r) * K + k0 + g * 8, 16);
    }
    #pragma unroll
    for (int i = 0; i < 4; i++) {
        int ch = tid + 256 * i;
        int r = ch >> 3, g = ch & 7;
        int br = col0 + r;
        int ok = (br < M);
        const __nv_bfloat16* src = BT + (size_t)(ok ? br : 0) * K + k0 + g * 8;
        cpa16(Bs0 + (unsigned)(stage * 9216 + r * 72 + g * 8) * 2, src, ok ? 16 : 0);
    }
}
__device__ __forceinline__ void hcompute(const __nv_bfloat16* As, const __nv_bfloat16* Bs,
                                         int stage, int wm, int wn, int lane,
                                         float acc[2][8][4])
{
    const int g = lane >> 2, q2 = (lane & 3) * 2;
    #pragma unroll
    for (int kk = 0; kk < 64; kk += 16) {
        unsigned a[2][4];
        #pragma unroll
        for (int mf = 0; mf < 2; mf++) {
            const __nv_bfloat16* p = As + stage * 9216 + (wm * 32 + mf * 16 + g) * 72;
            a[mf][0] = *(const unsigned*)(p + kk + q2);
            a[mf][1] = *(const unsigned*)(p + 8 * 72 + kk + q2);
            a[mf][2] = *(const unsigned*)(p + kk + 8 + q2);
            a[mf][3] = *(const unsigned*)(p + 8 * 72 + kk + 8 + q2);
        }
        #pragma unroll
        for (int nf = 0; nf < 8; nf++) {
            const __nv_bfloat16* bp = Bs + stage * 9216 + (wn * 64 + nf * 8 + g) * 72 + kk + q2;
            unsigned b0 = *(const unsigned*)bp;
            unsigned b1 = *(const unsigned*)(bp + 8);
            mma_bf16(acc[0][nf], a[0], b0, b1);
            mma_bf16(acc[1][nf], a[1], b0, b1);
        }
    }
}

template<int RELU, int L1EPI>
__global__ __launch_bounds__(256) void hgemm_k(
    const __nv_bfloat16* __restrict__ A, const __nv_bfloat16* __restrict__ BT,
    const float* __restrict__ bias, __nv_bfloat16* __restrict__ C, int K, int M,
    const float* __restrict__ Xref, float* __restrict__ part)
{
    extern __shared__ __align__(16) char sm[];
    __nv_bfloat16* As = (__nv_bfloat16*)sm;
    __nv_bfloat16* Bs = As + 2 * 128 * 72;
    float* red = (float*)(sm + 73728);

    const int tid = threadIdx.x;
    const int lane = tid & 31, wid = tid >> 5;
    const int wm = wid & 3, wn = wid >> 2;
    const int row0 = blockIdx.x * 128;
    const int col0 = blockIdx.y * 128;
    const unsigned As0 = smaddr(As), Bs0 = smaddr(Bs);

    float acc[2][8][4];
    #pragma unroll
    for (int a = 0; a < 2; a++)
        #pragma unroll
        for (int b = 0; b < 8; b++)
            #pragma unroll
            for (int c = 0; c < 4; c++) acc[a][b][c] = 0.f;

    const int nk = K >> 6;
    hfill(A, BT, As0, Bs0, 0, 0, row0, col0, K, M, tid);
    CP_COMMIT;
    for (int kc = 0; kc < nk; kc++) {
        if (kc + 1 < nk) {
            hfill(A, BT, As0, Bs0, (kc + 1) & 1, (kc + 1) * 64, row0, col0, K, M, tid);
            CP_COMMIT;
            cp_wait<1>();
        } else {
            cp_wait<0>();
        }
        __syncthreads();
        hcompute(As, Bs, kc & 1, wm, wn, lane, acc);
        __syncthreads();
    }

    const int g = lane >> 2, q2 = (lane & 3) * 2;
    if (!L1EPI) {
        #pragma unroll
        for (int mf = 0; mf < 2; mf++) {
            int r1 = row0 + wm * 32 + mf * 16 + g;
            #pragma unroll
            for (int nf = 0; nf < 8; nf++) {
                int cc = col0 + wn * 64 + nf * 8 + q2;
                float v0 = acc[mf][nf][0] + bias[cc];
                float v1 = acc[mf][nf][1] + bias[cc + 1];
                float v2 = acc[mf][nf][2] + bias[cc];
                float v3 = acc[mf][nf][3] + bias[cc + 1];
                if (RELU) {
                    v0 = fmaxf(v0, 0.f); v1 = fmaxf(v1, 0.f);
                    v2 = fmaxf(v2, 0.f); v3 = fmaxf(v3, 0.f);
                }
                __nv_bfloat162 h0; h0.x = __float2bfloat16(v0); h0.y = __float2bfloat16(v1);
                __nv_bfloat162 h1; h1.x = __float2bfloat16(v2); h1.y = __float2bfloat16(v3);
                *(__nv_bfloat162*)(C + (size_t)r1 * M + cc) = h0;
                *(__nv_bfloat162*)(C + (size_t)(r1 + 8) * M + cc) = h1;
            }
        }
    } else {
        float s = 0.f;
        #pragma unroll
        for (int mf = 0; mf < 2; mf++) {
            int r1 = row0 + wm * 32 + mf * 16 + g;
            #pragma unroll
            for (int nf = 0; nf < 8; nf++) {
                int cc = col0 + wn * 64 + nf * 8 + q2;
                #pragma unroll
                for (int e = 0; e < 4; e++) {
                    int c = cc + (e & 1);
                    int r = r1 + (e >= 2 ? 8 : 0);
                    if (c < M) {
                        float v = acc[mf][nf][e] + bias[c];
                        s += fabsf(Xref[(size_t)r * M + c] - v);
                    }
                }
            }
        }
        red[tid] = s;
        __syncthreads();
        #pragma unroll
        for (int off = 128; off > 0; off >>= 1) {
            if (tid < off) red[tid] += red[tid + off];
            __syncthreads();
        }
        if (tid == 0) part[blockIdx.x] = red[0];
    }
}

// ================= fused bf16 VQ (unchanged from round 2) =================
#define VQ_SMEM 221696

template<int Q>
__global__ __launch_bounds__(256) void vqscore_k(
    const float* __restrict__ rg, const __nv_bfloat16* __restrict__ cbh,
    const float* __restrict__ cbf, const float* __restrict__ cn,
    float* __restrict__ codes_out, float* __restrict__ res_out,
    float* __restrict__ q1buf, __nv_bfloat16* __restrict__ qbf,
    float* __restrict__ vqpart)
{
    extern __shared__ __align__(16) char sm[];
    __nv_bfloat16* As = (__nv_bfloat16*)sm;
    __nv_bfloat16* Bs = (__nv_bfloat16*)(sm + 67584);
    int*      cand   = (int*)     (sm + 202752);
    unsigned* rowmin = (unsigned*)(sm + 219136);
    int*      cnt    = (int*)     (sm + 219648);
    int*      chosen = (int*)     (sm + 220160);
    float*    red    = (float*)   (sm + 220672);

    const int tid = threadIdx.x;
    const int lane = tid & 31, wid = tid >> 5;
    const int wm = wid & 3, wn = wid >> 2;
    const size_t row0 = (size_t)blockIdx.x * 128;
    const unsigned Bs0 = smaddr(Bs);
    const int g = lane >> 2, q2 = (lane & 3) * 2;

    if (tid < 128) { rowmin[tid] = 0xFFFFFFFFu; cnt[tid] = 0; }

    #pragma unroll
    for (int i = 0; i < 32; i++) {
        int e = tid + 256 * i;
        int r = e >> 6, c4 = e & 63;
        float4 v = *(const float4*)(rg + (row0 + r) * 256 + 4 * c4);
        __nv_bfloat162 h0; h0.x = __float2bfloat16(v.x); h0.y = __float2bfloat16(v.y);
        __nv_bfloat162 h1; h1.x = __float2bfloat16(v.z); h1.y = __float2bfloat16(v.w);
        *(__nv_bfloat162*)(As + r * 264 + 4 * c4) = h0;
        *(__nv_bfloat162*)(As + r * 264 + 4 * c4 + 2) = h1;
    }
    __syncthreads();

    #pragma unroll
    for (int i = 0; i < 16; i++) {
        int ch = tid + 256 * i;
        int r = ch >> 5, gg = ch & 31;
        cpa16(Bs0 + (unsigned)(r * 264 + gg * 8) * 2,
              cbh + (size_t)r * 256 + gg * 8, 16);
    }
    CP_COMMIT;

    for (int t = 0; t < 8; t++) {
        if (t < 7) {
            int st = (t + 1) & 1;
            #pragma unroll
            for (int i = 0; i < 16; i++) {
                int ch = tid + 256 * i;
                int r = ch >> 5, gg = ch & 31;
                cpa16(Bs0 + (unsigned)(st * 33792 + r * 264 + gg * 8) * 2,
                      cbh + (size_t)((t + 1) * 128 + r) * 256 + gg * 8, 16);
            }
            CP_COMMIT;
            cp_wait<1>();
        } else {
            cp_wait<0>();
        }
        __syncthreads();

        float acc[2][8][4];
        #pragma unroll
        for (int a = 0; a < 2; a++)
            #pragma unroll
            for (int b = 0; b < 8; b++)
                #pragma unroll
                for (int c = 0; c < 4; c++) acc[a][b][c] = 0.f;

        const __nv_bfloat16* Bst = Bs + (t & 1) * 33792;
        #pragma unroll
        for (int kk = 0; kk < 256; kk += 16) {
            unsigned a[2][4];
            #pragma unroll
            for (int mf = 0; mf < 2; mf++) {
                const __nv_bfloat16* p = As + (wm * 32 + mf * 16 + g) * 264;
                a[mf][0] = *(const unsigned*)(p + kk + q2);
                a[mf][1] = *(const unsigned*)(p + 8 * 264 + kk + q2);
                a[mf][2] = *(const unsigned*)(p + kk + 8 + q2);
                a[mf][3] = *(const unsigned*)(p + 8 * 264 + kk + 8 + q2);
            }
            #pragma unroll
            for (int nf = 0; nf < 8; nf++) {
                const __nv_bfloat16* bp = Bst + (wn * 64 + nf * 8 + g) * 264 + kk + q2;
                unsigned b0 = *(const unsigned*)bp;
                unsigned b1 = *(const unsigned*)(bp + 8);
                mma_bf16(acc[0][nf], a[0], b0, b1);
                mma_bf16(acc[1][nf], a[1], b0, b1);
            }
        }

        #pragma unroll
        for (int mf = 0; mf < 2; mf++) {
            int r1 = wm * 32 + mf * 16 + g;
            float m1 = 1e30f, m2 = 1e30f;
            #pragma unroll
            for (int nf = 0; nf < 8; nf++) {
                int cl = wn * 64 + nf * 8 + q2;
                float cn0 = __ldg(cn + t * 128 + cl);
                float cn1 = __ldg(cn + t * 128 + cl + 1);
                float s0 = cn0 - acc[mf][nf][0];
                float s1 = cn1 - acc[mf][nf][1];
                float s2 = cn0 - acc[mf][nf][2];
                float s3 = cn1 - acc[mf][nf][3];
                acc[mf][nf][0] = s0; acc[mf][nf][1] = s1;
                acc[mf][nf][2] = s2; acc[mf][nf][3] = s3;
                m1 = fminf(m1, fminf(s0, s1));
                m2 = fminf(m2, fminf(s2, s3));
            }
            atomicMin(&rowmin[r1], fford(m1));
            atomicMin(&rowmin[r1 + 8], fford(m2));
        }
        __syncthreads();
        #pragma unroll
        for (int mf = 0; mf < 2; mf++) {
            int r1 = wm * 32 + mf * 16 + g;
            float thr1 = iford(rowmin[r1]) + MARGIN;
            float thr2 = iford(rowmin[r1 + 8]) + MARGIN;
            #pragma unroll
            for (int nf = 0; nf < 8; nf++) {
                int code = t * 128 + wn * 64 + nf * 8 + q2;
                #pragma unroll
                for (int e = 0; e < 4; e++) {
                    float s = acc[mf][nf][e];
                    int r = (e >= 2) ? (r1 + 8) : r1;
                    float thr = (e >= 2) ? thr2 : thr1;
                    if (s <= thr) {
                        int p = atomicAdd(&cnt[r], 1);
                        if (p < CAND_CAP) cand[r * CAND_CAP + p] = code + (e & 1);
                    }
                }
            }
        }
        __syncthreads();
    }

    for (int j = 0; j < 16; j++) {
        int row = wid + 8 * j;
        const float* rp = rg + (row0 + row) * 256 + lane * 8;
        float4 u = *(const float4*)rp;
        float4 v = *(const float4*)(rp + 4);
        float rr[8] = {u.x, u.y, u.z, u.w, v.x, v.y, v.z, v.w};
        int cv = cnt[row];
        float bv = 1e30f; int bc = 0;
        if (cv <= CAND_CAP) {
            for (int i = 0; i < cv; i++) {
                int c = cand[row * CAND_CAP + i];
                const float* cp = cbf + (size_t)c * 256 + lane * 8;
                float d = 0.f;
                #pragma unroll
                for (int e = 0; e < 8; e++) d = fmaf(rr[e], __ldg(cp + e), d);
                #pragma unroll
                for (int off = 16; off > 0; off >>= 1) d += __shfl_xor_sync(0xffffffff, d, off);
                float s = __ldg(cn + c) - d;
                if (s < bv || (s == bv && c < bc)) { bv = s; bc = c; }
            }
        } else {
            for (int c = 0; c < 1024; c++) {
                const float* cp = cbf + (size_t)c * 256 + lane * 8;
                float d = 0.f;
                #pragma unroll
                for (int e = 0; e < 8; e++) d = fmaf(rr[e], __ldg(cp + e), d);
                #pragma unroll
                for (int off = 16; off > 0; off >>= 1) d += __shfl_xor_sync(0xffffffff, d, off);
                float s = __ldg(cn + c) - d;
                if (s < bv || (s == bv && c < bc)) { bv = s; bc = c; }
            }
        }
        if (lane == 0) {
            chosen[row] = bc;
            codes_out[(row0 + row) * 2 + Q] = (float)bc;
        }
    }
    __syncthreads();

    float vac = 0.f;
    #pragma unroll
    for (int i = 0; i < 32; i++) {
        int e = tid + 256 * i;
        int r = e >> 6, c4 = e & 63;
        int c = chosen[r];
        size_t off = (row0 + r) * 256 + 4 * c4;
        float4 cvv = *(const float4*)(cbf + (size_t)c * 256 + 4 * c4);
        float4 zv  = *(const float4*)(rg + off);
        float4 dv = make_float4(zv.x - cvv.x, zv.y - cvv.y, zv.z - cvv.z, zv.w - cvv.w);
        vac += dv.x * dv.x + dv.y * dv.y + dv.z * dv.z + dv.w * dv.w;
        if (Q == 0) {
            *(float4*)(res_out + off) = dv;
            *(float4*)(q1buf + off) = cvv;
        } else {
            float4 q1v = *(const float4*)(q1buf + off);
            float4 sv = make_float4(q1v.x + cvv.x, q1v.y + cvv.y, q1v.z + cvv.z, q1v.w + cvv.w);
            __nv_bfloat162 h0; h0.x = __float2bfloat16(sv.x); h0.y = __float2bfloat16(sv.y);
            __nv_bfloat162 h1; h1.x = __float2bfloat16(sv.z); h1.y = __float2bfloat16(sv.w);
            *(__nv_bfloat162*)(qbf + off) = h0;
            *(__nv_bfloat162*)(qbf + off + 2) = h1;
        }
    }
    red[tid] = vac;
    __syncthreads();
    #pragma unroll
    for (int off = 128; off > 0; off >>= 1) {
        if (tid < off) red[tid] += red[tid + off];
        __syncthreads();
    }
    if (tid == 0) {
        if (Q == 0) vqpart[blockIdx.x] = red[0];
        else        vqpart[blockIdx.x] += red[0];
    }
}

// ================= final deterministic loss combine =================
__global__ __launch_bounds__(256) void final_k(
    const float* __restrict__ l1p, const float* __restrict__ vqp, float* __restrict__ out)
{
    __shared__ float sa[256], sb[256];
    float a = 0.f, b = 0.f;
    for (int i = threadIdx.x; i < RB128; i += 256) { a += l1p[i]; b += vqp[i]; }
    sa[threadIdx.x] = a; sb[threadIdx.x] = b;
    __syncthreads();
    #pragma unroll
    for (int off = 128; off > 0; off >>= 1) {
        if (threadIdx.x < off) {
            sa[threadIdx.x] += sa[threadIdx.x + off];
            sb[threadIdx.x] += sb[threadIdx.x + off];
        }
        __syncthreads();
    }
    if (threadIdx.x == 0) {
        float enc_loss = sa[0] / (131072.0f * 56.0f);
        float vq_loss  = sb[0] / (131072.0f * 256.0f);
        out[0] = enc_loss + 5.0f * vq_loss;
    }
}

// ================= launch =================
extern "C" void kernel_launch(void* const* d_in, const int* in_sizes, int n_in,
                              void* d_out, int out_size)
{
    const float* state = (const float*)d_in[0];
    const float* ew1 = (const float*)d_in[1];
    const float* eb1 = (const float*)d_in[2];
    const float* ew2 = (const float*)d_in[3];
    const float* eb2 = (const float*)d_in[4];
    const float* ew3 = (const float*)d_in[5];
    const float* eb3 = (const float*)d_in[6];
    const float* dw1 = (const float*)d_in[7];
    const float* db1 = (const float*)d_in[8];
    const float* dw2 = (const float*)d_in[9];
    const float* db2 = (const float*)d_in[10];
    const float* dw3 = (const float*)d_in[11];
    const float* db3 = (const float*)d_in[12];
    const float* cbk = (const float*)d_in[13];
    float* out = (float*)d_out;

    float *zb, *resb, *q1b, *cnp, *l1p, *vqp;
    __nv_bfloat16 *qbf, *dbA, *dbB, *spin, *sp1, *sp2, *wsp1, *wsp2, *wsp3, *cbh, *wt1, *wt2, *wt3;
    cudaGetSymbolAddress((void**)&zb,   g_z);
    cudaGetSymbolAddress((void**)&resb, g_res);
    cudaGetSymbolAddress((void**)&q1b,  g_q1);
    cudaGetSymbolAddress((void**)&qbf,  g_qbf);
    cudaGetSymbolAddress((void**)&dbA,  g_dbA);
    cudaGetSymbolAddress((void**)&dbB,  g_dbB);
    cudaGetSymbolAddress((void**)&spin, g_spin);
    cudaGetSymbolAddress((void**)&sp1,  g_sp1);
    cudaGetSymbolAddress((void**)&sp2,  g_sp2);
    cudaGetSymbolAddress((void**)&wsp1, g_wsp1);
    cudaGetSymbolAddress((void**)&wsp2, g_wsp2);
    cudaGetSymbolAddress((void**)&wsp3, g_wsp3);
    cudaGetSymbolAddress((void**)&cbh,  g_cbh);
    cudaGetSymbolAddress((void**)&wt1,  g_wt1);
    cudaGetSymbolAddress((void**)&wt2,  g_wt2);
    cudaGetSymbolAddress((void**)&wt3,  g_wt3);
    cudaGetSymbolAddress((void**)&cnp,  g_cn);
    cudaGetSymbolAddress((void**)&l1p,  g_l1p);
    cudaGetSymbolAddress((void**)&vqp,  g_vqp);

    cudaMemsetAsync(d_out, 0, (size_t)out_size * sizeof(float), 0);

    cudaFuncSetAttribute(vqscore_k<0>, cudaFuncAttributeMaxDynamicSharedMemorySize, VQ_SMEM);
    cudaFuncSetAttribute(vqscore_k<1>, cudaFuncAttributeMaxDynamicSharedMemorySize, VQ_SMEM);
    cudaFuncSetAttribute(hgemm_k<1,0>, cudaFuncAttributeMaxDynamicSharedMemorySize, 74752);
    cudaFuncSetAttribute(hgemm_k<0,1>, cudaFuncAttributeMaxDynamicSharedMemorySize, 74752);
    cudaFuncSetAttribute(shgemm_k<0>,  cudaFuncAttributeMaxDynamicSharedMemorySize, 74752);
    cudaFuncSetAttribute(shgemm_k<1>,  cudaFuncAttributeMaxDynamicSharedMemorySize, 74752);

    dim3 blk(256);

    // prep
    cn_k<<<256, blk>>>(cbk, cnp);
    cvt_k<<<(2*1024*256 + 255)/256, blk>>>(cbk, cbh, 2*1024*256);
    tr_k<<<(256*512 + 255)/256, blk>>>(dw1, wt1, 256, 512);
    tr_k<<<(512*512 + 255)/256, blk>>>(dw2, wt2, 512, 512);
    tr_k<<<(512*56  + 255)/256, blk>>>(dw3, wt3, 512, 56);
    split_state_k<<<(NROWS*64 + 255)/256, blk>>>(state, spin);
    split_w_k<<<(512*64  + 255)/256, blk>>>(ew1, wsp1,  56, 512,  64);
    split_w_k<<<(512*512 + 255)/256, blk>>>(ew2, wsp2, 512, 512, 512);
    split_w_k<<<(256*512 + 255)/256, blk>>>(ew3, wsp3, 512, 256, 512);

    // encoder: 3-way split bf16 HMMA (fp32-equivalent accuracy)
    shgemm_k<0><<<dim3(RB128, 4), blk, 74752>>>(spin, wsp1, eb1, sp1,  64, 512, 512);
    shgemm_k<0><<<dim3(RB128, 4), blk, 74752>>>(sp1,  wsp2, eb2, sp2, 512, 512, 512);
    shgemm_k<1><<<dim3(RB128, 2), blk, 74752>>>(sp2,  wsp3, eb3, zb,  512, 256, 0);

    // residual VQ (bf16 HMMA scoring + exact fp32 re-argmin)
    vqscore_k<0><<<RB128, blk, VQ_SMEM>>>(zb, cbh, cbk, cnp,
                                          out + 1, resb, q1b, nullptr, vqp);
    vqscore_k<1><<<RB128, blk, VQ_SMEM>>>(resb, cbh + 1024*256, cbk + 1024*256, cnp + 1024,
                                          out + 1, nullptr, q1b, qbf, vqp);

    // decoder
    hgemm_k<1,0><<<dim3(RB128, 4), blk, 74752>>>(qbf, wt1, db1, dbA, 256, 512, nullptr, nullptr);
    hgemm_k<1,0><<<dim3(RB128, 4), blk, 74752>>>(dbA, wt2, db2, dbB, 512, 512, nullptr, nullptr);
    hgemm_k<0,1><<<dim3(RB128, 1), blk, 74752>>>(dbB, wt3, db3, nullptr, 512, 56, state, l1p);

    final_k<<<1, 256>>>(l1p, vqp, out);
}

// round 6
// speedup vs baseline: 1.5492x; 1.5492x over previous
#include <cuda_runtime.h>
#include <cuda_bf16.h>
#include <math.h>

#define NROWS 131072
#define RB128 (NROWS/128)   // 1024
#define MARGIN 1.0f
#define CAND_CAP 32

// ---------------- scratch (device globals; no allocation allowed) ----------------
__device__ float g_z   [(size_t)NROWS * 256];
__device__ float g_res [(size_t)NROWS * 256];
__device__ float g_q1  [(size_t)NROWS * 256];
__device__ __nv_bfloat16 g_qbf [(size_t)NROWS * 256];
__device__ __nv_bfloat16 g_dbA [(size_t)NROWS * 512];
__device__ __nv_bfloat16 g_dbB [(size_t)NROWS * 512];
__device__ __nv_bfloat16 g_spin[(size_t)NROWS * 192];    // state split3, Kp=64
__device__ __nv_bfloat16 g_sp1 [(size_t)NROWS * 1536];   // h1 split3, Kp=512
__device__ __nv_bfloat16 g_sp2 [(size_t)NROWS * 1536];   // h2 split3, Kp=512
__device__ __nv_bfloat16 g_wsp1[512 * 192];
__device__ __nv_bfloat16 g_wsp2[512 * 1536];
__device__ __nv_bfloat16 g_wsp3[256 * 1536];
__device__ __nv_bfloat16 g_wt1[512 * 256];
__device__ __nv_bfloat16 g_wt2[512 * 512];
__device__ __nv_bfloat16 g_wt3[56 * 512];
__device__ __nv_bfloat16 g_cbh[2 * 1024 * 256];
__device__ float g_cn  [2 * 1024];
__device__ float g_l1p [RB128];
__device__ float g_vqp [RB128];

// ---------------- helpers ----------------
__device__ __forceinline__ unsigned smaddr(const void* p) {
    return (unsigned)__cvta_generic_to_shared(p);
}
__device__ __forceinline__ void cpa16(unsigned dst, const void* src, int sz) {
    asm volatile("cp.async.cg.shared.global [%0], [%1], 16, %2;\n"
                 :: "r"(dst), "l"(src), "r"(sz));
}
#define CP_COMMIT asm volatile("cp.async.commit_group;\n")
template<int N> __device__ __forceinline__ void cp_wait() {
    asm volatile("cp.async.wait_group %0;\n" :: "n"(N));
}
__device__ __forceinline__ void mma_bf16(float* c, const unsigned* a, unsigned b0, unsigned b1) {
    asm volatile(
        "mma.sync.aligned.m16n8k16.row.col.f32.bf16.bf16.f32 "
        "{%0,%1,%2,%3}, {%4,%5,%6,%7}, {%8,%9}, {%0,%1,%2,%3};\n"
        : "+f"(c[0]), "+f"(c[1]), "+f"(c[2]), "+f"(c[3])
        : "r"(a[0]), "r"(a[1]), "r"(a[2]), "r"(a[3]), "r"(b0), "r"(b1));
}
__device__ __forceinline__ void ldsm4(unsigned& r0, unsigned& r1, unsigned& r2, unsigned& r3,
                                      unsigned addr) {
    asm volatile("ldmatrix.sync.aligned.m8n8.x4.shared.b16 {%0,%1,%2,%3}, [%4];"
                 : "=r"(r0), "=r"(r1), "=r"(r2), "=r"(r3) : "r"(addr));
}
__device__ __forceinline__ unsigned fford(float f) {
    unsigned u = __float_as_uint(f);
    return (u & 0x80000000u) ? ~u : (u | 0x80000000u);
}
__device__ __forceinline__ float iford(unsigned u) {
    return __uint_as_float((u & 0x80000000u) ? (u ^ 0x80000000u) : ~u);
}
__device__ __forceinline__ void split3(float v, __nv_bfloat16& b0, __nv_bfloat16& b1, __nv_bfloat16& b2)
{
    b0 = __float2bfloat16(v);
    float r = v - __bfloat162float(b0);
    b1 = __float2bfloat16(r);
    float r2 = r - __bfloat162float(b1);
    b2 = __float2bfloat16(r2);
}
#define SWZ(r, cb) ((unsigned)((r) * 128 + ((cb) ^ (((r) & 7) << 4))))

// ================= unified mma.sync bf16 GEMM engine (v2) =================
// C[rows, M] = A[rows, LDA-chunks] x BT[M, LDA-chunks]^T
// tile: 128 rows x 128 cols, 256 threads (8 warps: 4 row-groups x 2 col-halves),
// K-chunk 64 bf16, SW128-swizzled smem, ldmatrix fragment loads, 3-stage cp.async.
// OUT: 0 = f32 (+bias), 1 = relu+split3 planes, 2 = relu+bf16, 3 = L1 partials vs Xref.
template<int KP, int SPLIT, int OUT>
__global__ __launch_bounds__(256) void mgemm(
    const __nv_bfloat16* __restrict__ A, const __nv_bfloat16* __restrict__ BT,
    const float* __restrict__ bias, void* __restrict__ Cv, int M, int KpN,
    const float* __restrict__ Xref, float* __restrict__ part)
{
    constexpr int NKC = KP / 64;
    constexpr int NCH = SPLIT ? 6 * NKC : NKC;
    constexpr int LDA = SPLIT ? 3 * KP : KP;

    extern __shared__ __align__(16) char dynsm[];
    __shared__ float s_red[256];

    const int tid = threadIdx.x;
    const int lane = tid & 31, wid = tid >> 5;
    const int wm = wid & 3, wn = wid >> 2;
    const int row0 = blockIdx.x * 128;
    const int col0 = blockIdx.y * 128;

    unsigned dynb = (smaddr(dynsm) + 1023u) & ~1023u;
    unsigned Ab[3], Bb[3];
    #pragma unroll
    for (int s = 0; s < 3; s++) { Ab[s] = dynb + s * 32768u; Bb[s] = Ab[s] + 16384u; }

    float acc[2][8][4];
    #pragma unroll
    for (int a = 0; a < 2; a++)
        #pragma unroll
        for (int b = 0; b < 8; b++)
            #pragma unroll
            for (int c = 0; c < 4; c++) acc[a][b][c] = 0.f;

    auto choff = [&](int c, int& aoff, int& boff) {
        if (!SPLIT) { aoff = boff = c * 64; }
        else {
            constexpr int PI[6] = {2, 1, 0, 0, 1, 0};
            constexpr int PJ[6] = {0, 1, 2, 1, 0, 0};
            int pr = c / NKC, kc = c - pr * NKC;
            aoff = PI[pr] * KP + kc * 64;
            boff = PJ[pr] * KP + kc * 64;
        }
    };
    auto fill = [&](int s, int c) {
        int aoff, boff; choff(c, aoff, boff);
        #pragma unroll
        for (int i = 0; i < 4; i++) {          // A: 128 rows x 128B
            int ch = tid + 256 * i;
            int r = ch >> 3, g = ch & 7;
            cpa16(Ab[s] + SWZ(r, g * 16),
                  A + (size_t)(row0 + r) * LDA + aoff + g * 8, 16);
        }
        #pragma unroll
        for (int i = 0; i < 4; i++) {          // B: 128 rows x 128B
            int ch = tid + 256 * i;
            int r = ch >> 3, g = ch & 7;
            int br = col0 + r;
            int ok = (br < M);
            const __nv_bfloat16* src = BT + (size_t)(ok ? br : 0) * LDA + boff + g * 8;
            cpa16(Bb[s] + SWZ(r, g * 16), src, ok ? 16 : 0);
        }
    };

    // ldmatrix per-thread addressing: tile quadrant from lane
    const int lrow = ((lane >> 3) & 1) * 8 + (lane & 7);   // row within 16-row tile
    const int lcb  = (lane >= 16) ? 16 : 0;                // 16B column within k16

    fill(0, 0); CP_COMMIT;
    fill(1, 1); CP_COMMIT;

    for (int c = 0; c < NCH; c++) {
        const int s = c % 3;
        if (c + 1 < NCH) cp_wait<1>(); else cp_wait<0>();
        __syncthreads();
        if (c + 2 < NCH) { fill((c + 2) % 3, c + 2); CP_COMMIT; }

        const unsigned Aw = Ab[s], Bw = Bb[s];
        #pragma unroll
        for (int kk = 0; kk < 64; kk += 16) {
            unsigned a[2][4];
            #pragma unroll
            for (int mf = 0; mf < 2; mf++) {
                int r = wm * 32 + mf * 16 + lrow;
                ldsm4(a[mf][0], a[mf][1], a[mf][2], a[mf][3], Aw + SWZ(r, kk * 2 + lcb));
            }
            unsigned bq[4][4];
            #pragma unroll
            for (int h = 0; h < 4; h++) {
                int r = wn * 64 + h * 16 + lrow;
                ldsm4(bq[h][0], bq[h][1], bq[h][2], bq[h][3], Bw + SWZ(r, kk * 2 + lcb));
            }
            #pragma unroll
            for (int nf = 0; nf < 8; nf++) {
                int h = nf >> 1, o = nf & 1;
                mma_bf16(acc[0][nf], a[0], bq[h][o], bq[h][o + 2]);
                mma_bf16(acc[1][nf], a[1], bq[h][o], bq[h][o + 2]);
            }
        }
        __syncthreads();
    }

    // ---- epilogue (fragment layout identical to rounds 2/3) ----
    const int g = lane >> 2, q2 = (lane & 3) * 2;
    if (OUT == 0) {
        float* C = (float*)Cv;
        #pragma unroll
        for (int mf = 0; mf < 2; mf++) {
            int r1 = row0 + wm * 32 + mf * 16 + g;
            #pragma unroll
            for (int nf = 0; nf < 8; nf++) {
                int cc = col0 + wn * 64 + nf * 8 + q2;
                float2 o0 = make_float2(acc[mf][nf][0] + bias[cc], acc[mf][nf][1] + bias[cc + 1]);
                float2 o1 = make_float2(acc[mf][nf][2] + bias[cc], acc[mf][nf][3] + bias[cc + 1]);
                *(float2*)(C + (size_t)r1 * M + cc) = o0;
                *(float2*)(C + (size_t)(r1 + 8) * M + cc) = o1;
            }
        }
    } else if (OUT == 1) {
        __nv_bfloat16* C = (__nv_bfloat16*)Cv;
        const size_t strd = 3 * (size_t)KpN;
        #pragma unroll
        for (int mf = 0; mf < 2; mf++) {
            int r1 = row0 + wm * 32 + mf * 16 + g;
            #pragma unroll
            for (int nf = 0; nf < 8; nf++) {
                int cc = col0 + wn * 64 + nf * 8 + q2;
                #pragma unroll
                for (int half = 0; half < 2; half++) {
                    int r = r1 + (half ? 8 : 0);
                    float v0 = fmaxf(acc[mf][nf][2 * half + 0] + bias[cc], 0.f);
                    float v1 = fmaxf(acc[mf][nf][2 * half + 1] + bias[cc + 1], 0.f);
                    __nv_bfloat16 a0, a1, a2, b0, b1, b2;
                    split3(v0, a0, a1, a2);
                    split3(v1, b0, b1, b2);
                    __nv_bfloat16* base = C + (size_t)r * strd + cc;
                    __nv_bfloat162 p0; p0.x = a0; p0.y = b0;
                    __nv_bfloat162 p1; p1.x = a1; p1.y = b1;
                    __nv_bfloat162 p2; p2.x = a2; p2.y = b2;
                    *(__nv_bfloat162*)(base)           = p0;
                    *(__nv_bfloat162*)(base + KpN)     = p1;
                    *(__nv_bfloat162*)(base + 2 * KpN) = p2;
                }
            }
        }
    } else if (OUT == 2) {
        __nv_bfloat16* C = (__nv_bfloat16*)Cv;
        #pragma unroll
        for (int mf = 0; mf < 2; mf++) {
            int r1 = row0 + wm * 32 + mf * 16 + g;
            #pragma unroll
            for (int nf = 0; nf < 8; nf++) {
                int cc = col0 + wn * 64 + nf * 8 + q2;
                float v0 = fmaxf(acc[mf][nf][0] + bias[cc], 0.f);
                float v1 = fmaxf(acc[mf][nf][1] + bias[cc + 1], 0.f);
                float v2 = fmaxf(acc[mf][nf][2] + bias[cc], 0.f);
                float v3 = fmaxf(acc[mf][nf][3] + bias[cc + 1], 0.f);
                __nv_bfloat162 h0; h0.x = __float2bfloat16(v0); h0.y = __float2bfloat16(v1);
                __nv_bfloat162 h1; h1.x = __float2bfloat16(v2); h1.y = __float2bfloat16(v3);
                *(__nv_bfloat162*)(C + (size_t)r1 * M + cc) = h0;
                *(__nv_bfloat162*)(C + (size_t)(r1 + 8) * M + cc) = h1;
            }
        }
    } else {
        float s = 0.f;
        #pragma unroll
        for (int mf = 0; mf < 2; mf++) {
            int r1 = row0 + wm * 32 + mf * 16 + g;
            #pragma unroll
            for (int nf = 0; nf < 8; nf++) {
                int cc = col0 + wn * 64 + nf * 8 + q2;
                #pragma unroll
                for (int e = 0; e < 4; e++) {
                    int c = cc + (e & 1);
                    int r = r1 + (e >= 2 ? 8 : 0);
                    if (c < M) {
                        float v = acc[mf][nf][e] + bias[c];
                        s += fabsf(Xref[(size_t)r * M + c] - v);
                    }
                }
            }
        }
        s_red[tid] = s;
        __syncthreads();
        #pragma unroll
        for (int off = 128; off > 0; off >>= 1) {
            if (tid < off) s_red[tid] += s_red[tid + off];
            __syncthreads();
        }
        if (tid == 0) part[blockIdx.x] = s_red[0];
    }
}

// ================= prep kernels =================
__global__ __launch_bounds__(256) void cn_k(const float* __restrict__ cb, float* __restrict__ cn)
{
    int w = (blockIdx.x * blockDim.x + threadIdx.x) >> 5;
    int lane = threadIdx.x & 31;
    if (w < 2048) {
        const float* c = cb + (size_t)w * 256;
        float s = 0.f;
        #pragma unroll
        for (int k = lane; k < 256; k += 32) s = fmaf(c[k], c[k], s);
        #pragma unroll
        for (int off = 16; off > 0; off >>= 1) s += __shfl_xor_sync(0xffffffff, s, off);
        if (lane == 0) cn[w] = 0.5f * s;
    }
}
__global__ __launch_bounds__(256) void cvt_k(const float* __restrict__ src,
                                             __nv_bfloat16* __restrict__ dst, int n)
{
    int i = blockIdx.x * 256 + threadIdx.x;
    if (i < n) dst[i] = __float2bfloat16(src[i]);
}
__global__ __launch_bounds__(256) void tr_k(const float* __restrict__ W,
                                            __nv_bfloat16* __restrict__ BT, int K, int M)
{
    int i = blockIdx.x * 256 + threadIdx.x;
    if (i < K * M) {
        int k = i / M, m = i % M;
        BT[(size_t)m * K + k] = __float2bfloat16(W[i]);
    }
}
__global__ __launch_bounds__(256) void split_state_k(const float* __restrict__ S,
                                                     __nv_bfloat16* __restrict__ D)
{
    long i = (long)blockIdx.x * 256 + threadIdx.x;
    if (i < (long)NROWS * 64) {
        long n = i >> 6; int k = (int)(i & 63);
        float v = (k < 56) ? S[n * 56 + k] : 0.f;
        __nv_bfloat16 b0, b1, b2;
        split3(v, b0, b1, b2);
        __nv_bfloat16* d = D + n * 192;
        d[k] = b0; d[64 + k] = b1; d[128 + k] = b2;
    }
}
__global__ __launch_bounds__(256) void split_w_k(const float* __restrict__ W,
                                                 __nv_bfloat16* __restrict__ BT,
                                                 int K, int M, int Kp)
{
    long i = (long)blockIdx.x * 256 + threadIdx.x;
    if (i < (long)M * Kp) {
        int m = (int)(i / Kp), k = (int)(i % Kp);
        float v = (k < K) ? W[(size_t)k * M + m] : 0.f;
        __nv_bfloat16 b0, b1, b2;
        split3(v, b0, b1, b2);
        __nv_bfloat16* d = BT + (size_t)m * 3 * Kp;
        d[k] = b0; d[Kp + k] = b1; d[2 * Kp + k] = b2;
    }
}

// ================= fused bf16 VQ (HMMA scoring + exact fp32 re-argmin) =================
#define VQ_SMEM 221696

template<int Q>
__global__ __launch_bounds__(256) void vqscore_k(
    const float* __restrict__ rg, const __nv_bfloat16* __restrict__ cbh,
    const float* __restrict__ cbf, const float* __restrict__ cn,
    float* __restrict__ codes_out, float* __restrict__ res_out,
    float* __restrict__ q1buf, __nv_bfloat16* __restrict__ qbf,
    float* __restrict__ vqpart)
{
    extern __shared__ __align__(16) char sm[];
    __nv_bfloat16* As = (__nv_bfloat16*)sm;
    __nv_bfloat16* Bs = (__nv_bfloat16*)(sm + 67584);
    int*      cand   = (int*)     (sm + 202752);
    unsigned* rowmin = (unsigned*)(sm + 219136);
    int*      cnt    = (int*)     (sm + 219648);
    int*      chosen = (int*)     (sm + 220160);
    float*    red    = (float*)   (sm + 220672);

    const int tid = threadIdx.x;
    const int lane = tid & 31, wid = tid >> 5;
    const int wm = wid & 3, wn = wid >> 2;
    const size_t row0 = (size_t)blockIdx.x * 128;
    const unsigned Bs0 = smaddr(Bs);
    const int g = lane >> 2, q2 = (lane & 3) * 2;

    if (tid < 128) { rowmin[tid] = 0xFFFFFFFFu; cnt[tid] = 0; }

    #pragma unroll
    for (int i = 0; i < 32; i++) {
        int e = tid + 256 * i;
        int r = e >> 6, c4 = e & 63;
        float4 v = *(const float4*)(rg + (row0 + r) * 256 + 4 * c4);
        __nv_bfloat162 h0; h0.x = __float2bfloat16(v.x); h0.y = __float2bfloat16(v.y);
        __nv_bfloat162 h1; h1.x = __float2bfloat16(v.z); h1.y = __float2bfloat16(v.w);
        *(__nv_bfloat162*)(As + r * 264 + 4 * c4) = h0;
        *(__nv_bfloat162*)(As + r * 264 + 4 * c4 + 2) = h1;
    }
    __syncthreads();

    #pragma unroll
    for (int i = 0; i < 16; i++) {
        int ch = tid + 256 * i;
        int r = ch >> 5, gg = ch & 31;
        cpa16(Bs0 + (unsigned)(r * 264 + gg * 8) * 2,
              cbh + (size_t)r * 256 + gg * 8, 16);
    }
    CP_COMMIT;

    for (int t = 0; t < 8; t++) {
        if (t < 7) {
            int st = (t + 1) & 1;
            #pragma unroll
            for (int i = 0; i < 16; i++) {
                int ch = tid + 256 * i;
                int r = ch >> 5, gg = ch & 31;
                cpa16(Bs0 + (unsigned)(st * 33792 + r * 264 + gg * 8) * 2,
                      cbh + (size_t)((t + 1) * 128 + r) * 256 + gg * 8, 16);
            }
            CP_COMMIT;
            cp_wait<1>();
        } else {
            cp_wait<0>();
        }
        __syncthreads();

        float acc[2][8][4];
        #pragma unroll
        for (int a = 0; a < 2; a++)
            #pragma unroll
            for (int b = 0; b < 8; b++)
                #pragma unroll
                for (int c = 0; c < 4; c++) acc[a][b][c] = 0.f;

        const __nv_bfloat16* Bst = Bs + (t & 1) * 33792;
        #pragma unroll
        for (int kk = 0; kk < 256; kk += 16) {
            unsigned a[2][4];
            #pragma unroll
            for (int mf = 0; mf < 2; mf++) {
                const __nv_bfloat16* p = As + (wm * 32 + mf * 16 + g) * 264;
                a[mf][0] = *(const unsigned*)(p + kk + q2);
                a[mf][1] = *(const unsigned*)(p + 8 * 264 + kk + q2);
                a[mf][2] = *(const unsigned*)(p + kk + 8 + q2);
                a[mf][3] = *(const unsigned*)(p + 8 * 264 + kk + 8 + q2);
            }
            #pragma unroll
            for (int nf = 0; nf < 8; nf++) {
                const __nv_bfloat16* bp = Bst + (wn * 64 + nf * 8 + g) * 264 + kk + q2;
                unsigned b0 = *(const unsigned*)bp;
                unsigned b1 = *(const unsigned*)(bp + 8);
                mma_bf16(acc[0][nf], a[0], b0, b1);
                mma_bf16(acc[1][nf], a[1], b0, b1);
            }
        }

        #pragma unroll
        for (int mf = 0; mf < 2; mf++) {
            int r1 = wm * 32 + mf * 16 + g;
            float m1 = 1e30f, m2 = 1e30f;
            #pragma unroll
            for (int nf = 0; nf < 8; nf++) {
                int cl = wn * 64 + nf * 8 + q2;
                float cn0 = __ldg(cn + t * 128 + cl);
                float cn1 = __ldg(cn + t * 128 + cl + 1);
                float s0 = cn0 - acc[mf][nf][0];
                float s1 = cn1 - acc[mf][nf][1];
                float s2 = cn0 - acc[mf][nf][2];
                float s3 = cn1 - acc[mf][nf][3];
                acc[mf][nf][0] = s0; acc[mf][nf][1] = s1;
                acc[mf][nf][2] = s2; acc[mf][nf][3] = s3;
                m1 = fminf(m1, fminf(s0, s1));
                m2 = fminf(m2, fminf(s2, s3));
            }
            atomicMin(&rowmin[r1], fford(m1));
            atomicMin(&rowmin[r1 + 8], fford(m2));
        }
        __syncthreads();
        #pragma unroll
        for (int mf = 0; mf < 2; mf++) {
            int r1 = wm * 32 + mf * 16 + g;
            float thr1 = iford(rowmin[r1]) + MARGIN;
            float thr2 = iford(rowmin[r1 + 8]) + MARGIN;
            #pragma unroll
            for (int nf = 0; nf < 8; nf++) {
                int code = t * 128 + wn * 64 + nf * 8 + q2;
                #pragma unroll
                for (int e = 0; e < 4; e++) {
                    float s = acc[mf][nf][e];
                    int r = (e >= 2) ? (r1 + 8) : r1;
                    float thr = (e >= 2) ? thr2 : thr1;
                    if (s <= thr) {
                        int p = atomicAdd(&cnt[r], 1);
                        if (p < CAND_CAP) cand[r * CAND_CAP + p] = code + (e & 1);
                    }
                }
            }
        }
        __syncthreads();
    }

    for (int j = 0; j < 16; j++) {
        int row = wid + 8 * j;
        const float* rp = rg + (row0 + row) * 256 + lane * 8;
        float4 u = *(const float4*)rp;
        float4 v = *(const float4*)(rp + 4);
        float rr[8] = {u.x, u.y, u.z, u.w, v.x, v.y, v.z, v.w};
        int cv = cnt[row];
        float bv = 1e30f; int bc = 0;
        if (cv <= CAND_CAP) {
            for (int i = 0; i < cv; i++) {
                int c = cand[row * CAND_CAP + i];
                const float* cp = cbf + (size_t)c * 256 + lane * 8;
                float d = 0.f;
                #pragma unroll
                for (int e = 0; e < 8; e++) d = fmaf(rr[e], __ldg(cp + e), d);
                #pragma unroll
                for (int off = 16; off > 0; off >>= 1) d += __shfl_xor_sync(0xffffffff, d, off);
                float s = __ldg(cn + c) - d;
                if (s < bv || (s == bv && c < bc)) { bv = s; bc = c; }
            }
        } else {
            for (int c = 0; c < 1024; c++) {
                const float* cp = cbf + (size_t)c * 256 + lane * 8;
                float d = 0.f;
                #pragma unroll
                for (int e = 0; e < 8; e++) d = fmaf(rr[e], __ldg(cp + e), d);
                #pragma unroll
                for (int off = 16; off > 0; off >>= 1) d += __shfl_xor_sync(0xffffffff, d, off);
                float s = __ldg(cn + c) - d;
                if (s < bv || (s == bv && c < bc)) { bv = s; bc = c; }
            }
        }
        if (lane == 0) {
            chosen[row] = bc;
            codes_out[(row0 + row) * 2 + Q] = (float)bc;
        }
    }
    __syncthreads();

    float vac = 0.f;
    #pragma unroll
    for (int i = 0; i < 32; i++) {
        int e = tid + 256 * i;
        int r = e >> 6, c4 = e & 63;
        int c = chosen[r];
        size_t off = (row0 + r) * 256 + 4 * c4;
        float4 cvv = *(const float4*)(cbf + (size_t)c * 256 + 4 * c4);
        float4 zv  = *(const float4*)(rg + off);
        float4 dv = make_float4(zv.x - cvv.x, zv.y - cvv.y, zv.z - cvv.z, zv.w - cvv.w);
        vac += dv.x * dv.x + dv.y * dv.y + dv.z * dv.z + dv.w * dv.w;
        if (Q == 0) {
            *(float4*)(res_out + off) = dv;
            *(float4*)(q1buf + off) = cvv;
        } else {
            float4 q1v = *(const float4*)(q1buf + off);
            float4 sv = make_float4(q1v.x + cvv.x, q1v.y + cvv.y, q1v.z + cvv.z, q1v.w + cvv.w);
            __nv_bfloat162 h0; h0.x = __float2bfloat16(sv.x); h0.y = __float2bfloat16(sv.y);
            __nv_bfloat162 h1; h1.x = __float2bfloat16(sv.z); h1.y = __float2bfloat16(sv.w);
            *(__nv_bfloat162*)(qbf + off) = h0;
            *(__nv_bfloat162*)(qbf + off + 2) = h1;
        }
    }
    red[tid] = vac;
    __syncthreads();
    #pragma unroll
    for (int off = 128; off > 0; off >>= 1) {
        if (tid < off) red[tid] += red[tid + off];
        __syncthreads();
    }
    if (tid == 0) {
        if (Q == 0) vqpart[blockIdx.x] = red[0];
        else        vqpart[blockIdx.x] += red[0];
    }
}

// ================= final deterministic loss combine =================
__global__ __launch_bounds__(256) void final_k(
    const float* __restrict__ l1p, const float* __restrict__ vqp, float* __restrict__ out)
{
    __shared__ float sa[256], sb[256];
    float a = 0.f, b = 0.f;
    for (int i = threadIdx.x; i < RB128; i += 256) { a += l1p[i]; b += vqp[i]; }
    sa[threadIdx.x] = a; sb[threadIdx.x] = b;
    __syncthreads();
    #pragma unroll
    for (int off = 128; off > 0; off >>= 1) {
        if (threadIdx.x < off) {
            sa[threadIdx.x] += sa[threadIdx.x + off];
            sb[threadIdx.x] += sb[threadIdx.x + off];
        }
        __syncthreads();
    }
    if (threadIdx.x == 0) {
        float enc_loss = sa[0] / (131072.0f * 56.0f);
        float vq_loss  = sb[0] / (131072.0f * 256.0f);
        out[0] = enc_loss + 5.0f * vq_loss;
    }
}

// ================= launch =================
extern "C" void kernel_launch(void* const* d_in, const int* in_sizes, int n_in,
                              void* d_out, int out_size)
{
    const float* state = (const float*)d_in[0];
    const float* ew1 = (const float*)d_in[1];
    const float* eb1 = (const float*)d_in[2];
    const float* ew2 = (const float*)d_in[3];
    const float* eb2 = (const float*)d_in[4];
    const float* ew3 = (const float*)d_in[5];
    const float* eb3 = (const float*)d_in[6];
    const float* dw1 = (const float*)d_in[7];
    const float* db1 = (const float*)d_in[8];
    const float* dw2 = (const float*)d_in[9];
    const float* db2 = (const float*)d_in[10];
    const float* dw3 = (const float*)d_in[11];
    const float* db3 = (const float*)d_in[12];
    const float* cbk = (const float*)d_in[13];
    float* out = (float*)d_out;

    float *zb, *resb, *q1b, *cnp, *l1p, *vqp;
    __nv_bfloat16 *qbf, *dbA, *dbB, *spin, *sp1, *sp2, *wsp1, *wsp2, *wsp3, *cbh, *wt1, *wt2, *wt3;
    cudaGetSymbolAddress((void**)&zb,   g_z);
    cudaGetSymbolAddress((void**)&resb, g_res);
    cudaGetSymbolAddress((void**)&q1b,  g_q1);
    cudaGetSymbolAddress((void**)&qbf,  g_qbf);
    cudaGetSymbolAddress((void**)&dbA,  g_dbA);
    cudaGetSymbolAddress((void**)&dbB,  g_dbB);
    cudaGetSymbolAddress((void**)&spin, g_spin);
    cudaGetSymbolAddress((void**)&sp1,  g_sp1);
    cudaGetSymbolAddress((void**)&sp2,  g_sp2);
    cudaGetSymbolAddress((void**)&wsp1, g_wsp1);
    cudaGetSymbolAddress((void**)&wsp2, g_wsp2);
    cudaGetSymbolAddress((void**)&wsp3, g_wsp3);
    cudaGetSymbolAddress((void**)&cbh,  g_cbh);
    cudaGetSymbolAddress((void**)&wt1,  g_wt1);
    cudaGetSymbolAddress((void**)&wt2,  g_wt2);
    cudaGetSymbolAddress((void**)&wt3,  g_wt3);
    cudaGetSymbolAddress((void**)&cnp,  g_cn);
    cudaGetSymbolAddress((void**)&l1p,  g_l1p);
    cudaGetSymbolAddress((void**)&vqp,  g_vqp);

    cudaMemsetAsync(d_out, 0, (size_t)out_size * sizeof(float), 0);

    const int DSM = 1024 + 3 * 32768;   // 99328
    cudaFuncSetAttribute(mgemm<64, 1, 1>,  cudaFuncAttributeMaxDynamicSharedMemorySize, DSM);
    cudaFuncSetAttribute(mgemm<512, 1, 1>, cudaFuncAttributeMaxDynamicSharedMemorySize, DSM);
    cudaFuncSetAttribute(mgemm<512, 1, 0>, cudaFuncAttributeMaxDynamicSharedMemorySize, DSM);
    cudaFuncSetAttribute(mgemm<256, 0, 2>, cudaFuncAttributeMaxDynamicSharedMemorySize, DSM);
    cudaFuncSetAttribute(mgemm<512, 0, 2>, cudaFuncAttributeMaxDynamicSharedMemorySize, DSM);
    cudaFuncSetAttribute(mgemm<512, 0, 3>, cudaFuncAttributeMaxDynamicSharedMemorySize, DSM);
    cudaFuncSetAttribute(vqscore_k<0>, cudaFuncAttributeMaxDynamicSharedMemorySize, VQ_SMEM);
    cudaFuncSetAttribute(vqscore_k<1>, cudaFuncAttributeMaxDynamicSharedMemorySize, VQ_SMEM);

    dim3 blk(256);

    // prep
    cn_k<<<256, blk>>>(cbk, cnp);
    cvt_k<<<(2*1024*256 + 255)/256, blk>>>(cbk, cbh, 2*1024*256);
    tr_k<<<(256*512 + 255)/256, blk>>>(dw1, wt1, 256, 512);
    tr_k<<<(512*512 + 255)/256, blk>>>(dw2, wt2, 512, 512);
    tr_k<<<(512*56  + 255)/256, blk>>>(dw3, wt3, 512, 56);
    split_state_k<<<(NROWS*64 + 255)/256, blk>>>(state, spin);
    split_w_k<<<(512*64  + 255)/256, blk>>>(ew1, wsp1,  56, 512,  64);
    split_w_k<<<(512*512 + 255)/256, blk>>>(ew2, wsp2, 512, 512, 512);
    split_w_k<<<(256*512 + 255)/256, blk>>>(ew3, wsp3, 512, 256, 512);

    // encoder: split3 bf16 (fp32-equivalent accuracy, proven in round 3)
    mgemm<64, 1, 1><<<dim3(RB128, 4), blk, DSM>>>(spin, wsp1, eb1, sp1, 512, 512, nullptr, nullptr);
    mgemm<512, 1, 1><<<dim3(RB128, 4), blk, DSM>>>(sp1, wsp2, eb2, sp2, 512, 512, nullptr, nullptr);
    mgemm<512, 1, 0><<<dim3(RB128, 2), blk, DSM>>>(sp2, wsp3, eb3, zb, 256, 0, nullptr, nullptr);

    // residual VQ (HMMA scoring + exact fp32 re-argmin)
    vqscore_k<0><<<RB128, blk, VQ_SMEM>>>(zb, cbh, cbk, cnp,
                                          out + 1, resb, q1b, nullptr, vqp);
    vqscore_k<1><<<RB128, blk, VQ_SMEM>>>(resb, cbh + 1024*256, cbk + 1024*256, cnp + 1024,
                                          out + 1, nullptr, q1b, qbf, vqp);

    // decoder (bf16; only affects the scalar mean)
    mgemm<256, 0, 2><<<dim3(RB128, 4), blk, DSM>>>(qbf, wt1, db1, dbA, 512, 0, nullptr, nullptr);
    mgemm<512, 0, 2><<<dim3(RB128, 4), blk, DSM>>>(dbA, wt2, db2, dbB, 512, 0, nullptr, nullptr);
    mgemm<512, 0, 3><<<dim3(RB128, 1), blk, DSM>>>(dbB, wt3, db3, nullptr, 56, 0, state, l1p);

    final_k<<<1, 256>>>(l1p, vqp, out);
}

// round 7
// speedup vs baseline: 2.2148x; 1.4296x over previous
#include <cuda_runtime.h>
#include <cuda_bf16.h>
#include <cuda_fp16.h>
#include <math.h>

#define NROWS 131072
#define RB128 (NROWS/128)   // 1024
#define MARGIN 1.0f
#define CAND_CAP 32

// ---------------- scratch (device globals; no allocation allowed) ----------------
__device__ float g_z   [(size_t)NROWS * 256];
__device__ float g_res [(size_t)NROWS * 256];
__device__ float g_q1  [(size_t)NROWS * 256];
__device__ __nv_bfloat16 g_qbf [(size_t)NROWS * 256];
__device__ __nv_bfloat16 g_dbA [(size_t)NROWS * 512];
__device__ __nv_bfloat16 g_dbB [(size_t)NROWS * 512];
__device__ __half g_spin[(size_t)NROWS * 128];    // state split2 fp16, Kp=64
__device__ __half g_sp1 [(size_t)NROWS * 1024];   // h1 split2, Kp=512
__device__ __half g_sp2 [(size_t)NROWS * 1024];   // h2 split2, Kp=512
__device__ __half g_wsp1[512 * 128];
__device__ __half g_wsp2[512 * 1024];
__device__ __half g_wsp3[256 * 1024];
__device__ __nv_bfloat16 g_wt1[512 * 256];
__device__ __nv_bfloat16 g_wt2[512 * 512];
__device__ __nv_bfloat16 g_wt3[56 * 512];
__device__ __nv_bfloat16 g_cbh[2 * 1024 * 256];
__device__ float g_cn  [2 * 1024];
__device__ float g_l1p [RB128];
__device__ float g_vqp [RB128];

// ---------------- helpers ----------------
__device__ __forceinline__ unsigned smaddr(const void* p) {
    return (unsigned)__cvta_generic_to_shared(p);
}
__device__ __forceinline__ void cpa16(unsigned dst, const void* src, int sz) {
    asm volatile("cp.async.cg.shared.global [%0], [%1], 16, %2;\n"
                 :: "r"(dst), "l"(src), "r"(sz));
}
#define CP_COMMIT asm volatile("cp.async.commit_group;\n")
template<int N> __device__ __forceinline__ void cp_wait() {
    asm volatile("cp.async.wait_group %0;\n" :: "n"(N));
}
__device__ __forceinline__ void mma_bf16(float* c, const unsigned* a, unsigned b0, unsigned b1) {
    asm volatile(
        "mma.sync.aligned.m16n8k16.row.col.f32.bf16.bf16.f32 "
        "{%0,%1,%2,%3}, {%4,%5,%6,%7}, {%8,%9}, {%0,%1,%2,%3};\n"
        : "+f"(c[0]), "+f"(c[1]), "+f"(c[2]), "+f"(c[3])
        : "r"(a[0]), "r"(a[1]), "r"(a[2]), "r"(a[3]), "r"(b0), "r"(b1));
}
__device__ __forceinline__ void mma_f16(float* c, const unsigned* a, unsigned b0, unsigned b1) {
    asm volatile(
        "mma.sync.aligned.m16n8k16.row.col.f32.f16.f16.f32 "
        "{%0,%1,%2,%3}, {%4,%5,%6,%7}, {%8,%9}, {%0,%1,%2,%3};\n"
        : "+f"(c[0]), "+f"(c[1]), "+f"(c[2]), "+f"(c[3])
        : "r"(a[0]), "r"(a[1]), "r"(a[2]), "r"(a[3]), "r"(b0), "r"(b1));
}
__device__ __forceinline__ void ldsm4(unsigned& r0, unsigned& r1, unsigned& r2, unsigned& r3,
                                      unsigned addr) {
    asm volatile("ldmatrix.sync.aligned.m8n8.x4.shared.b16 {%0,%1,%2,%3}, [%4];"
                 : "=r"(r0), "=r"(r1), "=r"(r2), "=r"(r3) : "r"(addr));
}
__device__ __forceinline__ unsigned fford(float f) {
    unsigned u = __float_as_uint(f);
    return (u & 0x80000000u) ? ~u : (u | 0x80000000u);
}
__device__ __forceinline__ float iford(unsigned u) {
    return __uint_as_float((u & 0x80000000u) ? (u ^ 0x80000000u) : ~u);
}
// 2-way fp16 decomposition: v ~= h0 + h1 to ~22 mantissa bits
__device__ __forceinline__ void split2h(float v, __half& h0, __half& h1)
{
    h0 = __float2half_rn(v);
    float r = v - __half2float(h0);
    h1 = __float2half_rn(r);
}
#define SWZ(r, cb) ((unsigned)((r) * 128 + ((cb) ^ (((r) & 7) << 4))))

// ================= unified mma.sync GEMM engine =================
// C[rows, M] = A[rows, LDA-chunks] x BT[M, LDA-chunks]^T
// tile: 128 rows x 128 cols, 256 threads (8 warps: 4 row-groups x 2 col-halves),
// K-chunk 64 elems (SW128 128B rows), ldmatrix fragments, 3-stage cp.async.
// SPLIT=1: fp16 split2 schedule (3 pairs, small->large); SPLIT=0: plain bf16.
// OUT: 0 = f32 (+bias), 1 = relu+split2 fp16 planes, 2 = relu+bf16, 3 = L1 partials.
template<int KP, int SPLIT, int OUT>
__global__ __launch_bounds__(256) void mgemm(
    const void* __restrict__ Av, const void* __restrict__ BTv,
    const float* __restrict__ bias, void* __restrict__ Cv, int M, int KpN,
    const float* __restrict__ Xref, float* __restrict__ part)
{
    constexpr int NKC = KP / 64;
    constexpr int NCH = SPLIT ? 3 * NKC : NKC;
    constexpr int LDA = SPLIT ? 2 * KP : KP;
    const unsigned short* A  = (const unsigned short*)Av;
    const unsigned short* BT = (const unsigned short*)BTv;

    extern __shared__ __align__(16) char dynsm[];
    __shared__ float s_red[256];

    const int tid = threadIdx.x;
    const int lane = tid & 31, wid = tid >> 5;
    const int wm = wid & 3, wn = wid >> 2;
    const int row0 = blockIdx.x * 128;
    const int col0 = blockIdx.y * 128;

    unsigned dynb = (smaddr(dynsm) + 1023u) & ~1023u;
    unsigned Ab[3], Bb[3];
    #pragma unroll
    for (int s = 0; s < 3; s++) { Ab[s] = dynb + s * 32768u; Bb[s] = Ab[s] + 16384u; }

    float acc[2][8][4];
    #pragma unroll
    for (int a = 0; a < 2; a++)
        #pragma unroll
        for (int b = 0; b < 8; b++)
            #pragma unroll
            for (int c = 0; c < 4; c++) acc[a][b][c] = 0.f;

    auto choff = [&](int c, int& aoff, int& boff) {
        if (!SPLIT) { aoff = boff = c * 64; }
        else {
            constexpr int PI[3] = {1, 0, 0};
            constexpr int PJ[3] = {0, 1, 0};
            int pr = c / NKC, kc = c - pr * NKC;
            aoff = PI[pr] * KP + kc * 64;
            boff = PJ[pr] * KP + kc * 64;
        }
    };
    auto fill = [&](int s, int c) {
        int aoff, boff; choff(c, aoff, boff);
        #pragma unroll
        for (int i = 0; i < 4; i++) {          // A: 128 rows x 128B
            int ch = tid + 256 * i;
            int r = ch >> 3, g = ch & 7;
            cpa16(Ab[s] + SWZ(r, g * 16),
                  A + (size_t)(row0 + r) * LDA + aoff + g * 8, 16);
        }
        #pragma unroll
        for (int i = 0; i < 4; i++) {          // B: 128 rows x 128B
            int ch = tid + 256 * i;
            int r = ch >> 3, g = ch & 7;
            int br = col0 + r;
            int ok = (br < M);
            const unsigned short* src = BT + (size_t)(ok ? br : 0) * LDA + boff + g * 8;
            cpa16(Bb[s] + SWZ(r, g * 16), src, ok ? 16 : 0);
        }
    };

    const int lrow = ((lane >> 3) & 1) * 8 + (lane & 7);
    const int lcb  = (lane >= 16) ? 16 : 0;

    fill(0, 0); CP_COMMIT;
    if (NCH > 1) { fill(1, 1); CP_COMMIT; }

    for (int c = 0; c < NCH; c++) {
        const int s = c % 3;
        if (c + 1 < NCH) cp_wait<1>(); else cp_wait<0>();
        __syncthreads();
        if (c + 2 < NCH) { fill((c + 2) % 3, c + 2); CP_COMMIT; }

        const unsigned Aw = Ab[s], Bw = Bb[s];
        #pragma unroll
        for (int kk = 0; kk < 64; kk += 16) {
            unsigned a[2][4];
            #pragma unroll
            for (int mf = 0; mf < 2; mf++) {
                int r = wm * 32 + mf * 16 + lrow;
                ldsm4(a[mf][0], a[mf][1], a[mf][2], a[mf][3], Aw + SWZ(r, kk * 2 + lcb));
            }
            unsigned bq[4][4];
            #pragma unroll
            for (int h = 0; h < 4; h++) {
                int r = wn * 64 + h * 16 + lrow;
                ldsm4(bq[h][0], bq[h][1], bq[h][2], bq[h][3], Bw + SWZ(r, kk * 2 + lcb));
            }
            #pragma unroll
            for (int nf = 0; nf < 8; nf++) {
                int h = nf >> 1, o = nf & 1;
                if (SPLIT) {
                    mma_f16(acc[0][nf], a[0], bq[h][o], bq[h][o + 2]);
                    mma_f16(acc[1][nf], a[1], bq[h][o], bq[h][o + 2]);
                } else {
                    mma_bf16(acc[0][nf], a[0], bq[h][o], bq[h][o + 2]);
                    mma_bf16(acc[1][nf], a[1], bq[h][o], bq[h][o + 2]);
                }
            }
        }
        __syncthreads();
    }

    // ---- epilogue (fragment layout identical to rounds 2/3/6) ----
    const int g = lane >> 2, q2 = (lane & 3) * 2;
    if (OUT == 0) {
        float* C = (float*)Cv;
        #pragma unroll
        for (int mf = 0; mf < 2; mf++) {
            int r1 = row0 + wm * 32 + mf * 16 + g;
            #pragma unroll
            for (int nf = 0; nf < 8; nf++) {
                int cc = col0 + wn * 64 + nf * 8 + q2;
                float2 o0 = make_float2(acc[mf][nf][0] + bias[cc], acc[mf][nf][1] + bias[cc + 1]);
                float2 o1 = make_float2(acc[mf][nf][2] + bias[cc], acc[mf][nf][3] + bias[cc + 1]);
                *(float2*)(C + (size_t)r1 * M + cc) = o0;
                *(float2*)(C + (size_t)(r1 + 8) * M + cc) = o1;
            }
        }
    } else if (OUT == 1) {
        __half* C = (__half*)Cv;
        const size_t strd = 2 * (size_t)KpN;
        #pragma unroll
        for (int mf = 0; mf < 2; mf++) {
            int r1 = row0 + wm * 32 + mf * 16 + g;
            #pragma unroll
            for (int nf = 0; nf < 8; nf++) {
                int cc = col0 + wn * 64 + nf * 8 + q2;
                #pragma unroll
                for (int half = 0; half < 2; half++) {
                    int r = r1 + (half ? 8 : 0);
                    float v0 = fmaxf(acc[mf][nf][2 * half + 0] + bias[cc], 0.f);
                    float v1 = fmaxf(acc[mf][nf][2 * half + 1] + bias[cc + 1], 0.f);
                    __half a0, a1, b0, b1;
                    split2h(v0, a0, a1);
                    split2h(v1, b0, b1);
                    __half* base = C + (size_t)r * strd + cc;
                    __half2 p0; p0.x = a0; p0.y = b0;
                    __half2 p1; p1.x = a1; p1.y = b1;
                    *(__half2*)(base)       = p0;
                    *(__half2*)(base + KpN) = p1;
                }
            }
        }
    } else if (OUT == 2) {
        __nv_bfloat16* C = (__nv_bfloat16*)Cv;
        #pragma unroll
        for (int mf = 0; mf < 2; mf++) {
            int r1 = row0 + wm * 32 + mf * 16 + g;
            #pragma unroll
            for (int nf = 0; nf < 8; nf++) {
                int cc = col0 + wn * 64 + nf * 8 + q2;
                float v0 = fmaxf(acc[mf][nf][0] + bias[cc], 0.f);
                float v1 = fmaxf(acc[mf][nf][1] + bias[cc + 1], 0.f);
                float v2 = fmaxf(acc[mf][nf][2] + bias[cc], 0.f);
                float v3 = fmaxf(acc[mf][nf][3] + bias[cc + 1], 0.f);
                __nv_bfloat162 h0; h0.x = __float2bfloat16(v0); h0.y = __float2bfloat16(v1);
                __nv_bfloat162 h1; h1.x = __float2bfloat16(v2); h1.y = __float2bfloat16(v3);
                *(__nv_bfloat162*)(C + (size_t)r1 * M + cc) = h0;
                *(__nv_bfloat162*)(C + (size_t)(r1 + 8) * M + cc) = h1;
            }
        }
    } else {
        float s = 0.f;
        #pragma unroll
        for (int mf = 0; mf < 2; mf++) {
            int r1 = row0 + wm * 32 + mf * 16 + g;
            #pragma unroll
            for (int nf = 0; nf < 8; nf++) {
                int cc = col0 + wn * 64 + nf * 8 + q2;
                #pragma unroll
                for (int e = 0; e < 4; e++) {
                    int c = cc + (e & 1);
                    int r = r1 + (e >= 2 ? 8 : 0);
                    if (c < M) {
                        float v = acc[mf][nf][e] + bias[c];
                        s += fabsf(Xref[(size_t)r * M + c] - v);
                    }
                }
            }
        }
        s_red[tid] = s;
        __syncthreads();
        #pragma unroll
        for (int off = 128; off > 0; off >>= 1) {
            if (tid < off) s_red[tid] += s_red[tid + off];
            __syncthreads();
        }
        if (tid == 0) part[blockIdx.x] = s_red[0];
    }
}

// ================= prep kernels =================
__global__ __launch_bounds__(256) void cn_k(const float* __restrict__ cb, float* __restrict__ cn)
{
    int w = (blockIdx.x * blockDim.x + threadIdx.x) >> 5;
    int lane = threadIdx.x & 31;
    if (w < 2048) {
        const float* c = cb + (size_t)w * 256;
        float s = 0.f;
        #pragma unroll
        for (int k = lane; k < 256; k += 32) s = fmaf(c[k], c[k], s);
        #pragma unroll
        for (int off = 16; off > 0; off >>= 1) s += __shfl_xor_sync(0xffffffff, s, off);
        if (lane == 0) cn[w] = 0.5f * s;
    }
}
__global__ __launch_bounds__(256) void cvt_k(const float* __restrict__ src,
                                             __nv_bfloat16* __restrict__ dst, int n)
{
    int i = blockIdx.x * 256 + threadIdx.x;
    if (i < n) dst[i] = __float2bfloat16(src[i]);
}
__global__ __launch_bounds__(256) void tr_k(const float* __restrict__ W,
                                            __nv_bfloat16* __restrict__ BT, int K, int M)
{
    int i = blockIdx.x * 256 + threadIdx.x;
    if (i < K * M) {
        int k = i / M, m = i % M;
        BT[(size_t)m * K + k] = __float2bfloat16(W[i]);
    }
}
__global__ __launch_bounds__(256) void split_state_k(const float* __restrict__ S,
                                                     __half* __restrict__ D)
{
    long i = (long)blockIdx.x * 256 + threadIdx.x;
    if (i < (long)NROWS * 64) {
        long n = i >> 6; int k = (int)(i & 63);
        float v = (k < 56) ? S[n * 56 + k] : 0.f;
        __half h0, h1;
        split2h(v, h0, h1);
        __half* d = D + n * 128;
        d[k] = h0; d[64 + k] = h1;
    }
}
__global__ __launch_bounds__(256) void split_w_k(const float* __restrict__ W,
                                                 __half* __restrict__ BT,
                                                 int K, int M, int Kp)
{
    long i = (long)blockIdx.x * 256 + threadIdx.x;
    if (i < (long)M * Kp) {
        int m = (int)(i / Kp), k = (int)(i % Kp);
        float v = (k < K) ? W[(size_t)k * M + m] : 0.f;
        __half h0, h1;
        split2h(v, h0, h1);
        __half* d = BT + (size_t)m * 2 * Kp;
        d[k] = h0; d[Kp + k] = h1;
    }
}

// ================= fused bf16 VQ (HMMA scoring + exact fp32 re-argmin) =================
#define VQ_SMEM 221696

template<int Q>
__global__ __launch_bounds__(256) void vqscore_k(
    const float* __restrict__ rg, const __nv_bfloat16* __restrict__ cbh,
    const float* __restrict__ cbf, const float* __restrict__ cn,
    float* __restrict__ codes_out, float* __restrict__ res_out,
    float* __restrict__ q1buf, __nv_bfloat16* __restrict__ qbf,
    float* __restrict__ vqpart)
{
    extern __shared__ __align__(16) char sm[];
    __nv_bfloat16* As = (__nv_bfloat16*)sm;
    __nv_bfloat16* Bs = (__nv_bfloat16*)(sm + 67584);
    int*      cand   = (int*)     (sm + 202752);
    unsigned* rowmin = (unsigned*)(sm + 219136);
    int*      cnt    = (int*)     (sm + 219648);
    int*      chosen = (int*)     (sm + 220160);
    float*    red    = (float*)   (sm + 220672);

    const int tid = threadIdx.x;
    const int lane = tid & 31, wid = tid >> 5;
    const int wm = wid & 3, wn = wid >> 2;
    const size_t row0 = (size_t)blockIdx.x * 128;
    const unsigned Bs0 = smaddr(Bs);
    const int g = lane >> 2, q2 = (lane & 3) * 2;

    if (tid < 128) { rowmin[tid] = 0xFFFFFFFFu; cnt[tid] = 0; }

    #pragma unroll
    for (int i = 0; i < 32; i++) {
        int e = tid + 256 * i;
        int r = e >> 6, c4 = e & 63;
        float4 v = *(const float4*)(rg + (row0 + r) * 256 + 4 * c4);
        __nv_bfloat162 h0; h0.x = __float2bfloat16(v.x); h0.y = __float2bfloat16(v.y);
        __nv_bfloat162 h1; h1.x = __float2bfloat16(v.z); h1.y = __float2bfloat16(v.w);
        *(__nv_bfloat162*)(As + r * 264 + 4 * c4) = h0;
        *(__nv_bfloat162*)(As + r * 264 + 4 * c4 + 2) = h1;
    }
    __syncthreads();

    #pragma unroll
    for (int i = 0; i < 16; i++) {
        int ch = tid + 256 * i;
        int r = ch >> 5, gg = ch & 31;
        cpa16(Bs0 + (unsigned)(r * 264 + gg * 8) * 2,
              cbh + (size_t)r * 256 + gg * 8, 16);
    }
    CP_COMMIT;

    for (int t = 0; t < 8; t++) {
        if (t < 7) {
            int st = (t + 1) & 1;
            #pragma unroll
            for (int i = 0; i < 16; i++) {
                int ch = tid + 256 * i;
                int r = ch >> 5, gg = ch & 31;
                cpa16(Bs0 + (unsigned)(st * 33792 + r * 264 + gg * 8) * 2,
                      cbh + (size_t)((t + 1) * 128 + r) * 256 + gg * 8, 16);
            }
            CP_COMMIT;
            cp_wait<1>();
        } else {
            cp_wait<0>();
        }
        __syncthreads();

        float acc[2][8][4];
        #pragma unroll
        for (int a = 0; a < 2; a++)
            #pragma unroll
            for (int b = 0; b < 8; b++)
                #pragma unroll
                for (int c = 0; c < 4; c++) acc[a][b][c] = 0.f;

        const __nv_bfloat16* Bst = Bs + (t & 1) * 33792;
        #pragma unroll
        for (int kk = 0; kk < 256; kk += 16) {
            unsigned a[2][4];
            #pragma unroll
            for (int mf = 0; mf < 2; mf++) {
                const __nv_bfloat16* p = As + (wm * 32 + mf * 16 + g) * 264;
                a[mf][0] = *(const unsigned*)(p + kk + q2);
                a[mf][1] = *(const unsigned*)(p + 8 * 264 + kk + q2);
                a[mf][2] = *(const unsigned*)(p + kk + 8 + q2);
                a[mf][3] = *(const unsigned*)(p + 8 * 264 + kk + 8 + q2);
            }
            #pragma unroll
            for (int nf = 0; nf < 8; nf++) {
                const __nv_bfloat16* bp = Bst + (wn * 64 + nf * 8 + g) * 264 + kk + q2;
                unsigned b0 = *(const unsigned*)bp;
                unsigned b1 = *(const unsigned*)(bp + 8);
                mma_bf16(acc[0][nf], a[0], b0, b1);
                mma_bf16(acc[1][nf], a[1], b0, b1);
            }
        }

        #pragma unroll
        for (int mf = 0; mf < 2; mf++) {
            int r1 = wm * 32 + mf * 16 + g;
            float m1 = 1e30f, m2 = 1e30f;
            #pragma unroll
            for (int nf = 0; nf < 8; nf++) {
                int cl = wn * 64 + nf * 8 + q2;
                float cn0 = __ldg(cn + t * 128 + cl);
                float cn1 = __ldg(cn + t * 128 + cl + 1);
                float s0 = cn0 - acc[mf][nf][0];
                float s1 = cn1 - acc[mf][nf][1];
                float s2 = cn0 - acc[mf][nf][2];
                float s3 = cn1 - acc[mf][nf][3];
                acc[mf][nf][0] = s0; acc[mf][nf][1] = s1;
                acc[mf][nf][2] = s2; acc[mf][nf][3] = s3;
                m1 = fminf(m1, fminf(s0, s1));
                m2 = fminf(m2, fminf(s2, s3));
            }
            atomicMin(&rowmin[r1], fford(m1));
            atomicMin(&rowmin[r1 + 8], fford(m2));
        }
        __syncthreads();
        #pragma unroll
        for (int mf = 0; mf < 2; mf++) {
            int r1 = wm * 32 + mf * 16 + g;
            float thr1 = iford(rowmin[r1]) + MARGIN;
            float thr2 = iford(rowmin[r1 + 8]) + MARGIN;
            #pragma unroll
            for (int nf = 0; nf < 8; nf++) {
                int code = t * 128 + wn * 64 + nf * 8 + q2;
                #pragma unroll
                for (int e = 0; e < 4; e++) {
                    float s = acc[mf][nf][e];
                    int r = (e >= 2) ? (r1 + 8) : r1;
                    float thr = (e >= 2) ? thr2 : thr1;
                    if (s <= thr) {
                        int p = atomicAdd(&cnt[r], 1);
                        if (p < CAND_CAP) cand[r * CAND_CAP + p] = code + (e & 1);
                    }
                }
            }
        }
        __syncthreads();
    }

    for (int j = 0; j < 16; j++) {
        int row = wid + 8 * j;
        const float* rp = rg + (row0 + row) * 256 + lane * 8;
        float4 u = *(const float4*)rp;
        float4 v = *(const float4*)(rp + 4);
        float rr[8] = {u.x, u.y, u.z, u.w, v.x, v.y, v.z, v.w};
        int cv = cnt[row];
        float bv = 1e30f; int bc = 0;
        if (cv <= CAND_CAP) {
            for (int i = 0; i < cv; i++) {
                int c = cand[row * CAND_CAP + i];
                const float* cp = cbf + (size_t)c * 256 + lane * 8;
                float d = 0.f;
                #pragma unroll
                for (int e = 0; e < 8; e++) d = fmaf(rr[e], __ldg(cp + e), d);
                #pragma unroll
                for (int off = 16; off > 0; off >>= 1) d += __shfl_xor_sync(0xffffffff, d, off);
                float s = __ldg(cn + c) - d;
                if (s < bv || (s == bv && c < bc)) { bv = s; bc = c; }
            }
        } else {
            for (int c = 0; c < 1024; c++) {
                const float* cp = cbf + (size_t)c * 256 + lane * 8;
                float d = 0.f;
                #pragma unroll
                for (int e = 0; e < 8; e++) d = fmaf(rr[e], __ldg(cp + e), d);
                #pragma unroll
                for (int off = 16; off > 0; off >>= 1) d += __shfl_xor_sync(0xffffffff, d, off);
                float s = __ldg(cn + c) - d;
                if (s < bv || (s == bv && c < bc)) { bv = s; bc = c; }
            }
        }
        if (lane == 0) {
            chosen[row] = bc;
            codes_out[(row0 + row) * 2 + Q] = (float)bc;
        }
    }
    __syncthreads();

    float vac = 0.f;
    #pragma unroll
    for (int i = 0; i < 32; i++) {
        int e = tid + 256 * i;
        int r = e >> 6, c4 = e & 63;
        int c = chosen[r];
        size_t off = (row0 + r) * 256 + 4 * c4;
        float4 cvv = *(const float4*)(cbf + (size_t)c * 256 + 4 * c4);
        float4 zv  = *(const float4*)(rg + off);
        float4 dv = make_float4(zv.x - cvv.x, zv.y - cvv.y, zv.z - cvv.z, zv.w - cvv.w);
        vac += dv.x * dv.x + dv.y * dv.y + dv.z * dv.z + dv.w * dv.w;
        if (Q == 0) {
            *(float4*)(res_out + off) = dv;
            *(float4*)(q1buf + off) = cvv;
        } else {
            float4 q1v = *(const float4*)(q1buf + off);
            float4 sv = make_float4(q1v.x + cvv.x, q1v.y + cvv.y, q1v.z + cvv.z, q1v.w + cvv.w);
            __nv_bfloat162 h0; h0.x = __float2bfloat16(sv.x); h0.y = __float2bfloat16(sv.y);
            __nv_bfloat162 h1; h1.x = __float2bfloat16(sv.z); h1.y = __float2bfloat16(sv.w);
            *(__nv_bfloat162*)(qbf + off) = h0;
            *(__nv_bfloat162*)(qbf + off + 2) = h1;
        }
    }
    red[tid] = vac;
    __syncthreads();
    #pragma unroll
    for (int off = 128; off > 0; off >>= 1) {
        if (tid < off) red[tid] += red[tid + off];
        __syncthreads();
    }
    if (tid == 0) {
        if (Q == 0) vqpart[blockIdx.x] = red[0];
        else        vqpart[blockIdx.x] += red[0];
    }
}

// ================= final deterministic loss combine =================
__global__ __launch_bounds__(256) void final_k(
    const float* __restrict__ l1p, const float* __restrict__ vqp, float* __restrict__ out)
{
    __shared__ float sa[256], sb[256];
    float a = 0.f, b = 0.f;
    for (int i = threadIdx.x; i < RB128; i += 256) { a += l1p[i]; b += vqp[i]; }
    sa[threadIdx.x] = a; sb[threadIdx.x] = b;
    __syncthreads();
    #pragma unroll
    for (int off = 128; off > 0; off >>= 1) {
        if (threadIdx.x < off) {
            sa[threadIdx.x] += sa[threadIdx.x + off];
            sb[threadIdx.x] += sb[threadIdx.x + off];
        }
        __syncthreads();
    }
    if (threadIdx.x == 0) {
        float enc_loss = sa[0] / (131072.0f * 56.0f);
        float vq_loss  = sb[0] / (131072.0f * 256.0f);
        out[0] = enc_loss + 5.0f * vq_loss;
    }
}

// ================= launch =================
extern "C" void kernel_launch(void* const* d_in, const int* in_sizes, int n_in,
                              void* d_out, int out_size)
{
    const float* state = (const float*)d_in[0];
    const float* ew1 = (const float*)d_in[1];
    const float* eb1 = (const float*)d_in[2];
    const float* ew2 = (const float*)d_in[3];
    const float* eb2 = (const float*)d_in[4];
    const float* ew3 = (const float*)d_in[5];
    const float* eb3 = (const float*)d_in[6];
    const float* dw1 = (const float*)d_in[7];
    const float* db1 = (const float*)d_in[8];
    const float* dw2 = (const float*)d_in[9];
    const float* db2 = (const float*)d_in[10];
    const float* dw3 = (const float*)d_in[11];
    const float* db3 = (const float*)d_in[12];
    const float* cbk = (const float*)d_in[13];
    float* out = (float*)d_out;

    float *zb, *resb, *q1b, *cnp, *l1p, *vqp;
    __nv_bfloat16 *qbf, *dbA, *dbB, *cbh, *wt1, *wt2, *wt3;
    __half *spin, *sp1, *sp2, *wsp1, *wsp2, *wsp3;
    cudaGetSymbolAddress((void**)&zb,   g_z);
    cudaGetSymbolAddress((void**)&resb, g_res);
    cudaGetSymbolAddress((void**)&q1b,  g_q1);
    cudaGetSymbolAddress((void**)&qbf,  g_qbf);
    cudaGetSymbolAddress((void**)&dbA,  g_dbA);
    cudaGetSymbolAddress((void**)&dbB,  g_dbB);
    cudaGetSymbolAddress((void**)&spin, g_spin);
    cudaGetSymbolAddress((void**)&sp1,  g_sp1);
    cudaGetSymbolAddress((void**)&sp2,  g_sp2);
    cudaGetSymbolAddress((void**)&wsp1, g_wsp1);
    cudaGetSymbolAddress((void**)&wsp2, g_wsp2);
    cudaGetSymbolAddress((void**)&wsp3, g_wsp3);
    cudaGetSymbolAddress((void**)&cbh,  g_cbh);
    cudaGetSymbolAddress((void**)&wt1,  g_wt1);
    cudaGetSymbolAddress((void**)&wt2,  g_wt2);
    cudaGetSymbolAddress((void**)&wt3,  g_wt3);
    cudaGetSymbolAddress((void**)&cnp,  g_cn);
    cudaGetSymbolAddress((void**)&l1p,  g_l1p);
    cudaGetSymbolAddress((void**)&vqp,  g_vqp);

    cudaMemsetAsync(d_out, 0, (size_t)out_size * sizeof(float), 0);

    const int DSM = 1024 + 3 * 32768;   // 99328
    cudaFuncSetAttribute(mgemm<64, 1, 1>,  cudaFuncAttributeMaxDynamicSharedMemorySize, DSM);
    cudaFuncSetAttribute(mgemm<512, 1, 1>, cudaFuncAttributeMaxDynamicSharedMemorySize, DSM);
    cudaFuncSetAttribute(mgemm<512, 1, 0>, cudaFuncAttributeMaxDynamicSharedMemorySize, DSM);
    cudaFuncSetAttribute(mgemm<256, 0, 2>, cudaFuncAttributeMaxDynamicSharedMemorySize, DSM);
    cudaFuncSetAttribute(mgemm<512, 0, 2>, cudaFuncAttributeMaxDynamicSharedMemorySize, DSM);
    cudaFuncSetAttribute(mgemm<512, 0, 3>, cudaFuncAttributeMaxDynamicSharedMemorySize, DSM);
    cudaFuncSetAttribute(vqscore_k<0>, cudaFuncAttributeMaxDynamicSharedMemorySize, VQ_SMEM);
    cudaFuncSetAttribute(vqscore_k<1>, cudaFuncAttributeMaxDynamicSharedMemorySize, VQ_SMEM);

    dim3 blk(256);

    // prep
    cn_k<<<256, blk>>>(cbk, cnp);
    cvt_k<<<(2*1024*256 + 255)/256, blk>>>(cbk, cbh, 2*1024*256);
    tr_k<<<(256*512 + 255)/256, blk>>>(dw1, wt1, 256, 512);
    tr_k<<<(512*512 + 255)/256, blk>>>(dw2, wt2, 512, 512);
    tr_k<<<(512*56  + 255)/256, blk>>>(dw3, wt3, 512, 56);
    split_state_k<<<(NROWS*64 + 255)/256, blk>>>(state, spin);
    split_w_k<<<(512*64  + 255)/256, blk>>>(ew1, wsp1,  56, 512,  64);
    split_w_k<<<(512*512 + 255)/256, blk>>>(ew2, wsp2, 512, 512, 512);
    split_w_k<<<(256*512 + 255)/256, blk>>>(ew3, wsp3, 512, 256, 512);

    // encoder: fp16 split2 (3 plane-pairs, ~22-bit mantissa fidelity)
    mgemm<64, 1, 1><<<dim3(RB128, 4), blk, DSM>>>(spin, wsp1, eb1, sp1, 512, 512, nullptr, nullptr);
    mgemm<512, 1, 1><<<dim3(RB128, 4), blk, DSM>>>(sp1, wsp2, eb2, sp2, 512, 512, nullptr, nullptr);
    mgemm<512, 1, 0><<<dim3(RB128, 2), blk, DSM>>>(sp2, wsp3, eb3, zb, 256, 0, nullptr, nullptr);

    // residual VQ (HMMA scoring + exact fp32 re-argmin)
    vqscore_k<0><<<RB128, blk, VQ_SMEM>>>(zb, cbh, cbk, cnp,
                                          out + 1, resb, q1b, nullptr, vqp);
    vqscore_k<1><<<RB128, blk, VQ_SMEM>>>(resb, cbh + 1024*256, cbk + 1024*256, cnp + 1024,
                                          out + 1, nullptr, q1b, qbf, vqp);

    // decoder (bf16; only affects the scalar mean)
    mgemm<256, 0, 2><<<dim3(RB128, 4), blk, DSM>>>(qbf, wt1, db1, dbA, 512, 0, nullptr, nullptr);
    mgemm<512, 0, 2><<<dim3(RB128, 4), blk, DSM>>>(dbA, wt2, db2, dbB, 512, 0, nullptr, nullptr);
    mgemm<512, 0, 3><<<dim3(RB128, 1), blk, DSM>>>(dbB, wt3, db3, nullptr, 56, 0, state, l1p);

    final_k<<<1, 256>>>(l1p, vqp, out);
}

// round 8
// speedup vs baseline: 2.3318x; 1.0528x over previous
#include <cuda_runtime.h>
#include <cuda_bf16.h>
#include <cuda_fp16.h>
#include <math.h>

#define NROWS 131072
#define RB128 (NROWS/128)   // 1024
#define MARGIN 1.0f
#define CAND_CAP 32

// ---------------- scratch (device globals; no allocation allowed) ----------------
__device__ float g_z   [(size_t)NROWS * 256];
__device__ float g_res [(size_t)NROWS * 256];
__device__ __nv_bfloat16 g_qbf [(size_t)NROWS * 256];
__device__ __nv_bfloat16 g_dbA [(size_t)NROWS * 512];
__device__ __nv_bfloat16 g_dbB [(size_t)NROWS * 512];
__device__ __half g_spin[(size_t)NROWS * 128];    // state split2 fp16, Kp=64
__device__ __half g_sp1 [(size_t)NROWS * 1024];   // h1 split2, Kp=512
__device__ __half g_sp2 [(size_t)NROWS * 1024];   // h2 split2, Kp=512
__device__ __half g_wsp1[512 * 128];
__device__ __half g_wsp2[512 * 1024];
__device__ __half g_wsp3[256 * 1024];
__device__ __nv_bfloat16 g_wt1[512 * 256];
__device__ __nv_bfloat16 g_wt2[512 * 512];
__device__ __nv_bfloat16 g_wt3[56 * 512];
__device__ __nv_bfloat16 g_cbh[2 * 1024 * 256];
__device__ float g_cn  [2 * 1024];
__device__ float g_l1p [RB128];
__device__ float g_vqp [RB128];

// ---------------- helpers ----------------
__device__ __forceinline__ unsigned smaddr(const void* p) {
    return (unsigned)__cvta_generic_to_shared(p);
}
__device__ __forceinline__ void cpa16(unsigned dst, const void* src, int sz) {
    asm volatile("cp.async.cg.shared.global [%0], [%1], 16, %2;\n"
                 :: "r"(dst), "l"(src), "r"(sz));
}
#define CP_COMMIT asm volatile("cp.async.commit_group;\n")
template<int N> __device__ __forceinline__ void cp_wait() {
    asm volatile("cp.async.wait_group %0;\n" :: "n"(N));
}
__device__ __forceinline__ void mma_bf16(float* c, const unsigned* a, unsigned b0, unsigned b1) {
    asm volatile(
        "mma.sync.aligned.m16n8k16.row.col.f32.bf16.bf16.f32 "
        "{%0,%1,%2,%3}, {%4,%5,%6,%7}, {%8,%9}, {%0,%1,%2,%3};\n"
        : "+f"(c[0]), "+f"(c[1]), "+f"(c[2]), "+f"(c[3])
        : "r"(a[0]), "r"(a[1]), "r"(a[2]), "r"(a[3]), "r"(b0), "r"(b1));
}
__device__ __forceinline__ void mma_f16(float* c, const unsigned* a, unsigned b0, unsigned b1) {
    asm volatile(
        "mma.sync.aligned.m16n8k16.row.col.f32.f16.f16.f32 "
        "{%0,%1,%2,%3}, {%4,%5,%6,%7}, {%8,%9}, {%0,%1,%2,%3};\n"
        : "+f"(c[0]), "+f"(c[1]), "+f"(c[2]), "+f"(c[3])
        : "r"(a[0]), "r"(a[1]), "r"(a[2]), "r"(a[3]), "r"(b0), "r"(b1));
}
__device__ __forceinline__ void ldsm4(unsigned& r0, unsigned& r1, unsigned& r2, unsigned& r3,
                                      unsigned addr) {
    asm volatile("ldmatrix.sync.aligned.m8n8.x4.shared.b16 {%0,%1,%2,%3}, [%4];"
                 : "=r"(r0), "=r"(r1), "=r"(r2), "=r"(r3) : "r"(addr));
}
__device__ __forceinline__ unsigned fford(float f) {
    unsigned u = __float_as_uint(f);
    return (u & 0x80000000u) ? ~u : (u | 0x80000000u);
}
__device__ __forceinline__ float iford(unsigned u) {
    return __uint_as_float((u & 0x80000000u) ? (u ^ 0x80000000u) : ~u);
}
__device__ __forceinline__ void split2h(float v, __half& h0, __half& h1)
{
    h0 = __float2half_rn(v);
    float r = v - __half2float(h0);
    h1 = __float2half_rn(r);
}
#define SWZ(r, cb) ((unsigned)((r) * 128 + ((cb) ^ (((r) & 7) << 4))))

// ================= unified mma.sync GEMM engine (unchanged from round 7) =================
template<int KP, int SPLIT, int OUT>
__global__ __launch_bounds__(256) void mgemm(
    const void* __restrict__ Av, const void* __restrict__ BTv,
    const float* __restrict__ bias, void* __restrict__ Cv, int M, int KpN,
    const float* __restrict__ Xref, float* __restrict__ part)
{
    constexpr int NKC = KP / 64;
    constexpr int NCH = SPLIT ? 3 * NKC : NKC;
    constexpr int LDA = SPLIT ? 2 * KP : KP;
    const unsigned short* A  = (const unsigned short*)Av;
    const unsigned short* BT = (const unsigned short*)BTv;

    extern __shared__ __align__(16) char dynsm[];
    __shared__ float s_red[256];

    const int tid = threadIdx.x;
    const int lane = tid & 31, wid = tid >> 5;
    const int wm = wid & 3, wn = wid >> 2;
    const int row0 = blockIdx.x * 128;
    const int col0 = blockIdx.y * 128;

    unsigned dynb = (smaddr(dynsm) + 1023u) & ~1023u;
    unsigned Ab[3], Bb[3];
    #pragma unroll
    for (int s = 0; s < 3; s++) { Ab[s] = dynb + s * 32768u; Bb[s] = Ab[s] + 16384u; }

    float acc[2][8][4];
    #pragma unroll
    for (int a = 0; a < 2; a++)
        #pragma unroll
        for (int b = 0; b < 8; b++)
            #pragma unroll
            for (int c = 0; c < 4; c++) acc[a][b][c] = 0.f;

    auto choff = [&](int c, int& aoff, int& boff) {
        if (!SPLIT) { aoff = boff = c * 64; }
        else {
            constexpr int PI[3] = {1, 0, 0};
            constexpr int PJ[3] = {0, 1, 0};
            int pr = c / NKC, kc = c - pr * NKC;
            aoff = PI[pr] * KP + kc * 64;
            boff = PJ[pr] * KP + kc * 64;
        }
    };
    auto fill = [&](int s, int c) {
        int aoff, boff; choff(c, aoff, boff);
        #pragma unroll
        for (int i = 0; i < 4; i++) {
            int ch = tid + 256 * i;
            int r = ch >> 3, g = ch & 7;
            cpa16(Ab[s] + SWZ(r, g * 16),
                  A + (size_t)(row0 + r) * LDA + aoff + g * 8, 16);
        }
        #pragma unroll
        for (int i = 0; i < 4; i++) {
            int ch = tid + 256 * i;
            int r = ch >> 3, g = ch & 7;
            int br = col0 + r;
            int ok = (br < M);
            const unsigned short* src = BT + (size_t)(ok ? br : 0) * LDA + boff + g * 8;
            cpa16(Bb[s] + SWZ(r, g * 16), src, ok ? 16 : 0);
        }
    };

    const int lrow = ((lane >> 3) & 1) * 8 + (lane & 7);
    const int lcb  = (lane >= 16) ? 16 : 0;

    fill(0, 0); CP_COMMIT;
    if (NCH > 1) { fill(1, 1); CP_COMMIT; }

    for (int c = 0; c < NCH; c++) {
        const int s = c % 3;
        if (c + 1 < NCH) cp_wait<1>(); else cp_wait<0>();
        __syncthreads();
        if (c + 2 < NCH) { fill((c + 2) % 3, c + 2); CP_COMMIT; }

        const unsigned Aw = Ab[s], Bw = Bb[s];
        #pragma unroll
        for (int kk = 0; kk < 64; kk += 16) {
            unsigned a[2][4];
            #pragma unroll
            for (int mf = 0; mf < 2; mf++) {
                int r = wm * 32 + mf * 16 + lrow;
                ldsm4(a[mf][0], a[mf][1], a[mf][2], a[mf][3], Aw + SWZ(r, kk * 2 + lcb));
            }
            unsigned bq[4][4];
            #pragma unroll
            for (int h = 0; h < 4; h++) {
                int r = wn * 64 + h * 16 + lrow;
                ldsm4(bq[h][0], bq[h][1], bq[h][2], bq[h][3], Bw + SWZ(r, kk * 2 + lcb));
            }
            #pragma unroll
            for (int nf = 0; nf < 8; nf++) {
                int h = nf >> 1, o = nf & 1;
                if (SPLIT) {
                    mma_f16(acc[0][nf], a[0], bq[h][o], bq[h][o + 2]);
                    mma_f16(acc[1][nf], a[1], bq[h][o], bq[h][o + 2]);
                } else {
                    mma_bf16(acc[0][nf], a[0], bq[h][o], bq[h][o + 2]);
                    mma_bf16(acc[1][nf], a[1], bq[h][o], bq[h][o + 2]);
                }
            }
        }
        __syncthreads();
    }

    const int g = lane >> 2, q2 = (lane & 3) * 2;
    if (OUT == 0) {
        float* C = (float*)Cv;
        #pragma unroll
        for (int mf = 0; mf < 2; mf++) {
            int r1 = row0 + wm * 32 + mf * 16 + g;
            #pragma unroll
            for (int nf = 0; nf < 8; nf++) {
                int cc = col0 + wn * 64 + nf * 8 + q2;
                float2 o0 = make_float2(acc[mf][nf][0] + bias[cc], acc[mf][nf][1] + bias[cc + 1]);
                float2 o1 = make_float2(acc[mf][nf][2] + bias[cc], acc[mf][nf][3] + bias[cc + 1]);
                *(float2*)(C + (size_t)r1 * M + cc) = o0;
                *(float2*)(C + (size_t)(r1 + 8) * M + cc) = o1;
            }
        }
    } else if (OUT == 1) {
        __half* C = (__half*)Cv;
        const size_t strd = 2 * (size_t)KpN;
        #pragma unroll
        for (int mf = 0; mf < 2; mf++) {
            int r1 = row0 + wm * 32 + mf * 16 + g;
            #pragma unroll
            for (int nf = 0; nf < 8; nf++) {
                int cc = col0 + wn * 64 + nf * 8 + q2;
                #pragma unroll
                for (int half = 0; half < 2; half++) {
                    int r = r1 + (half ? 8 : 0);
                    float v0 = fmaxf(acc[mf][nf][2 * half + 0] + bias[cc], 0.f);
                    float v1 = fmaxf(acc[mf][nf][2 * half + 1] + bias[cc + 1], 0.f);
                    __half a0, a1, b0, b1;
                    split2h(v0, a0, a1);
                    split2h(v1, b0, b1);
                    __half* base = C + (size_t)r * strd + cc;
                    __half2 p0; p0.x = a0; p0.y = b0;
                    __half2 p1; p1.x = a1; p1.y = b1;
                    *(__half2*)(base)       = p0;
                    *(__half2*)(base + KpN) = p1;
                }
            }
        }
    } else if (OUT == 2) {
        __nv_bfloat16* C = (__nv_bfloat16*)Cv;
        #pragma unroll
        for (int mf = 0; mf < 2; mf++) {
            int r1 = row0 + wm * 32 + mf * 16 + g;
            #pragma unroll
            for (int nf = 0; nf < 8; nf++) {
                int cc = col0 + wn * 64 + nf * 8 + q2;
                float v0 = fmaxf(acc[mf][nf][0] + bias[cc], 0.f);
                float v1 = fmaxf(acc[mf][nf][1] + bias[cc + 1], 0.f);
                float v2 = fmaxf(acc[mf][nf][2] + bias[cc], 0.f);
                float v3 = fmaxf(acc[mf][nf][3] + bias[cc + 1], 0.f);
                __nv_bfloat162 h0; h0.x = __float2bfloat16(v0); h0.y = __float2bfloat16(v1);
                __nv_bfloat162 h1; h1.x = __float2bfloat16(v2); h1.y = __float2bfloat16(v3);
                *(__nv_bfloat162*)(C + (size_t)r1 * M + cc) = h0;
                *(__nv_bfloat162*)(C + (size_t)(r1 + 8) * M + cc) = h1;
            }
        }
    } else {
        float s = 0.f;
        #pragma unroll
        for (int mf = 0; mf < 2; mf++) {
            int r1 = row0 + wm * 32 + mf * 16 + g;
            #pragma unroll
            for (int nf = 0; nf < 8; nf++) {
                int cc = col0 + wn * 64 + nf * 8 + q2;
                #pragma unroll
                for (int e = 0; e < 4; e++) {
                    int c = cc + (e & 1);
                    int r = r1 + (e >= 2 ? 8 : 0);
                    if (c < M) {
                        float v = acc[mf][nf][e] + bias[c];
                        s += fabsf(Xref[(size_t)r * M + c] - v);
                    }
                }
            }
        }
        s_red[tid] = s;
        __syncthreads();
        #pragma unroll
        for (int off = 128; off > 0; off >>= 1) {
            if (tid < off) s_red[tid] += s_red[tid + off];
            __syncthreads();
        }
        if (tid == 0) part[blockIdx.x] = s_red[0];
    }
}

// ================= fused prep kernel (all 9 prep ops, section-dispatched) =================
// sections (all multiples of 32): split_state 8388608 | cvt 524288 | tr1 131072 |
// tr2 262144 | tr3 28672 | sw1 32768 | sw2 262144 | sw3 131072 | cn 65536
__global__ __launch_bounds__(256) void prep_k(
    const float* __restrict__ state,
    const float* __restrict__ ew1, const float* __restrict__ ew2, const float* __restrict__ ew3,
    const float* __restrict__ dw1, const float* __restrict__ dw2, const float* __restrict__ dw3,
    const float* __restrict__ cbk,
    __half* __restrict__ spin, __half* __restrict__ wsp1, __half* __restrict__ wsp2,
    __half* __restrict__ wsp3,
    __nv_bfloat16* __restrict__ wt1, __nv_bfloat16* __restrict__ wt2,
    __nv_bfloat16* __restrict__ wt3, __nv_bfloat16* __restrict__ cbh,
    float* __restrict__ cnp)
{
    long gid = (long)blockIdx.x * 256 + threadIdx.x;

    if (gid < 8388608L) {                  // split_state: [N][56] -> [N][2*64] fp16
        long n = gid >> 6; int k = (int)(gid & 63);
        float v = (k < 56) ? state[n * 56 + k] : 0.f;
        __half h0, h1; split2h(v, h0, h1);
        __half* d = spin + n * 128;
        d[k] = h0; d[64 + k] = h1;
        return;
    }
    gid -= 8388608L;
    if (gid < 524288) {                    // codebook fp32 -> bf16
        cbh[gid] = __float2bfloat16(cbk[gid]);
        return;
    }
    gid -= 524288;
    if (gid < 131072) {                    // tr1: dw1 [256][512] -> wt1 [512][256]
        int k = (int)(gid / 512), m = (int)(gid % 512);
        wt1[(size_t)m * 256 + k] = __float2bfloat16(dw1[gid]);
        return;
    }
    gid -= 131072;
    if (gid < 262144) {                    // tr2: dw2 [512][512] -> wt2
        int k = (int)(gid / 512), m = (int)(gid % 512);
        wt2[(size_t)m * 512 + k] = __float2bfloat16(dw2[gid]);
        return;
    }
    gid -= 262144;
    if (gid < 28672) {                     // tr3: dw3 [512][56] -> wt3 [56][512]
        int k = (int)(gid / 56), m = (int)(gid % 56);
        wt3[(size_t)m * 512 + k] = __float2bfloat16(dw3[gid]);
        return;
    }
    gid -= 28672;
    if (gid < 32768) {                     // sw1: ew1 [56][512] -> wsp1 [512][2*64]
        int m = (int)(gid / 64), k = (int)(gid % 64);
        float v = (k < 56) ? ew1[(size_t)k * 512 + m] : 0.f;
        __half h0, h1; split2h(v, h0, h1);
        __half* d = wsp1 + (size_t)m * 128;
        d[k] = h0; d[64 + k] = h1;
        return;
    }
    gid -= 32768;
    if (gid < 262144) {                    // sw2: ew2 [512][512] -> wsp2 [512][2*512]
        int m = (int)(gid / 512), k = (int)(gid % 512);
        float v = ew2[(size_t)k * 512 + m];
        __half h0, h1; split2h(v, h0, h1);
        __half* d = wsp2 + (size_t)m * 1024;
        d[k] = h0; d[512 + k] = h1;
        return;
    }
    gid -= 262144;
    if (gid < 131072) {                    // sw3: ew3 [512][256] -> wsp3 [256][2*512]
        int m = (int)(gid / 512), k = (int)(gid % 512);
        float v = ew3[(size_t)k * 256 + m];
        __half h0, h1; split2h(v, h0, h1);
        __half* d = wsp3 + (size_t)m * 1024;
        d[k] = h0; d[512 + k] = h1;
        return;
    }
    gid -= 131072;
    if (gid < 65536) {                     // cn: half-norms, one warp per code
        int w = (int)(gid >> 5);
        int lane = (int)(gid & 31);
        const float* c = cbk + (size_t)w * 256;
        float s = 0.f;
        #pragma unroll
        for (int k = lane; k < 256; k += 32) s = fmaf(c[k], c[k], s);
        #pragma unroll
        for (int off = 16; off > 0; off >>= 1) s += __shfl_xor_sync(0xffffffff, s, off);
        if (lane == 0) cnp[w] = 0.5f * s;
    }
}
#define PREP_THREADS (8388608L + 524288 + 131072 + 262144 + 28672 + 32768 + 262144 + 131072 + 65536)
#define PREP_BLOCKS  ((int)((PREP_THREADS + 255) / 256))

// ================= fused bf16 VQ, ldmatrix engine (scores bitwise = round 7) =================
// dynamic smem layout (relative to 1024-aligned base):
//   As      : 0      .. 65536    (4 kb-blocks of [128 rows][128B], SWZ)
//   Bs      : 65536  .. 196608   (2 stages x 64KB, same structure)
//   cand    : 196608 .. 212992   int[128*32]
//   rowmin  : 212992 .. 213504
//   cnt     : 213504 .. 214016
//   chosen  : 214016 .. 214528
//   ch0     : 214528 .. 215040
//   red     : 215040 .. 216064
#define VQ_SMEM (216064 + 1024)

template<int Q>
__global__ __launch_bounds__(256) void vqscore_k(
    const float* __restrict__ rg, const __nv_bfloat16* __restrict__ cbh,
    const float* __restrict__ cbf, const float* __restrict__ cbf0,
    const float* __restrict__ cn,
    float* __restrict__ codes_out, float* __restrict__ res_out,
    __nv_bfloat16* __restrict__ qbf, float* __restrict__ vqpart)
{
    extern __shared__ __align__(16) char sm[];
    unsigned dynb = (smaddr(sm) + 1023u) & ~1023u;
    char* smc = sm + (int)(dynb - smaddr(sm));
    const unsigned AsB = dynb;
    const unsigned BsB = dynb + 65536u;
    int*      cand   = (int*)     (smc + 196608);
    unsigned* rowmin = (unsigned*)(smc + 212992);
    int*      cnt    = (int*)     (smc + 213504);
    int*      chosen = (int*)     (smc + 214016);
    int*      ch0    = (int*)     (smc + 214528);
    float*    red    = (float*)   (smc + 215040);

    const int tid = threadIdx.x;
    const int lane = tid & 31, wid = tid >> 5;
    const int wm = wid & 3, wn = wid >> 2;
    const size_t row0 = (size_t)blockIdx.x * 128;
    const int g = lane >> 2, q2 = (lane & 3) * 2;
    const int lrow = ((lane >> 3) & 1) * 8 + (lane & 7);
    const int lcb  = (lane >= 16) ? 16 : 0;

    if (tid < 128) {
        rowmin[tid] = 0xFFFFFFFFu;
        cnt[tid] = 0;
        if (Q == 1) ch0[tid] = (int)codes_out[(row0 + tid) * 2];
    }

    // A tile: fp32 -> bf16, swizzled store
    #pragma unroll
    for (int i = 0; i < 32; i++) {
        int e = tid + 256 * i;
        int r = e >> 6, c4 = e & 63;
        float4 v = *(const float4*)(rg + (row0 + r) * 256 + 4 * c4);
        __nv_bfloat162 h0; h0.x = __float2bfloat16(v.x); h0.y = __float2bfloat16(v.y);
        __nv_bfloat162 h1; h1.x = __float2bfloat16(v.z); h1.y = __float2bfloat16(v.w);
        uint2 p; p.x = *(unsigned*)&h0; p.y = *(unsigned*)&h1;
        int kb = c4 >> 4;
        unsigned off = (unsigned)kb * 16384u + (unsigned)r * 128u
                     + (((unsigned)((c4 * 8) & 127)) ^ (((unsigned)r & 7u) << 4));
        *(uint2*)(smc + off) = p;
    }
    __syncthreads();

    // prefetch B tile 0
    #pragma unroll
    for (int i = 0; i < 16; i++) {
        int ch = tid + 256 * i;
        int r = ch >> 5, gg = ch & 31;
        cpa16(BsB + (unsigned)(gg >> 3) * 16384u + SWZ(r, (gg & 7) * 16),
              cbh + (size_t)r * 256 + gg * 8, 16);
    }
    CP_COMMIT;

    for (int t = 0; t < 8; t++) {
        if (t < 7) {
            unsigned stb = BsB + (unsigned)((t + 1) & 1) * 65536u;
            #pragma unroll
            for (int i = 0; i < 16; i++) {
                int ch = tid + 256 * i;
                int r = ch >> 5, gg = ch & 31;
                cpa16(stb + (unsigned)(gg >> 3) * 16384u + SWZ(r, (gg & 7) * 16),
                      cbh + (size_t)((t + 1) * 128 + r) * 256 + gg * 8, 16);
            }
            CP_COMMIT;
            cp_wait<1>();
        } else {
            cp_wait<0>();
        }
        __syncthreads();

        float acc[2][8][4];
        #pragma unroll
        for (int a = 0; a < 2; a++)
            #pragma unroll
            for (int b = 0; b < 8; b++)
                #pragma unroll
                for (int c = 0; c < 4; c++) acc[a][b][c] = 0.f;

        const unsigned Bst = BsB + (unsigned)(t & 1) * 65536u;
        #pragma unroll
        for (int kk = 0; kk < 256; kk += 16) {
            int kb = kk >> 6;
            int kloc = (kk & 63) * 2;
            unsigned a[2][4];
            #pragma unroll
            for (int mf = 0; mf < 2; mf++) {
                int r = wm * 32 + mf * 16 + lrow;
                ldsm4(a[mf][0], a[mf][1], a[mf][2], a[mf][3],
                      AsB + (unsigned)kb * 16384u + SWZ(r, kloc + lcb));
            }
            unsigned bq[4][4];
            #pragma unroll
            for (int h = 0; h < 4; h++) {
                int r = wn * 64 + h * 16 + lrow;
                ldsm4(bq[h][0], bq[h][1], bq[h][2], bq[h][3],
                      Bst + (unsigned)kb * 16384u + SWZ(r, kloc + lcb));
            }
            #pragma unroll
            for (int nf = 0; nf < 8; nf++) {
                int h = nf >> 1, o = nf & 1;
                mma_bf16(acc[0][nf], a[0], bq[h][o], bq[h][o + 2]);
                mma_bf16(acc[1][nf], a[1], bq[h][o], bq[h][o + 2]);
            }
        }

        // scores s = cn - dot; per-thread min per row, then atomicMin
        #pragma unroll
        for (int mf = 0; mf < 2; mf++) {
            int r1 = wm * 32 + mf * 16 + g;
            float m1 = 1e30f, m2 = 1e30f;
            #pragma unroll
            for (int nf = 0; nf < 8; nf++) {
                int cl = wn * 64 + nf * 8 + q2;
                float cn0 = __ldg(cn + t * 128 + cl);
                float cn1 = __ldg(cn + t * 128 + cl + 1);
                float s0 = cn0 - acc[mf][nf][0];
                float s1 = cn1 - acc[mf][nf][1];
                float s2 = cn0 - acc[mf][nf][2];
                float s3 = cn1 - acc[mf][nf][3];
                acc[mf][nf][0] = s0; acc[mf][nf][1] = s1;
                acc[mf][nf][2] = s2; acc[mf][nf][3] = s3;
                m1 = fminf(m1, fminf(s0, s1));
                m2 = fminf(m2, fminf(s2, s3));
            }
            atomicMin(&rowmin[r1], fford(m1));
            atomicMin(&rowmin[r1 + 8], fford(m2));
        }
        __syncthreads();
        #pragma unroll
        for (int mf = 0; mf < 2; mf++) {
            int r1 = wm * 32 + mf * 16 + g;
            float thr1 = iford(rowmin[r1]) + MARGIN;
            float thr2 = iford(rowmin[r1 + 8]) + MARGIN;
            #pragma unroll
            for (int nf = 0; nf < 8; nf++) {
                int code = t * 128 + wn * 64 + nf * 8 + q2;
                #pragma unroll
                for (int e = 0; e < 4; e++) {
                    float s = acc[mf][nf][e];
                    int r = (e >= 2) ? (r1 + 8) : r1;
                    float thr = (e >= 2) ? thr2 : thr1;
                    if (s <= thr) {
                        int p = atomicAdd(&cnt[r], 1);
                        if (p < CAND_CAP) cand[r * CAND_CAP + p] = code + (e & 1);
                    }
                }
            }
        }
        __syncthreads();
    }

    // exact fp32 rescue: one warp per row, 16 rows per warp
    for (int j = 0; j < 16; j++) {
        int row = wid + 8 * j;
        const float* rp = rg + (row0 + row) * 256 + lane * 8;
        float4 u = *(const float4*)rp;
        float4 v = *(const float4*)(rp + 4);
        float rr[8] = {u.x, u.y, u.z, u.w, v.x, v.y, v.z, v.w};
        int cv = cnt[row];
        float bv = 1e30f; int bc = 0;
        if (cv <= CAND_CAP) {
            for (int i = 0; i < cv; i++) {
                int c = cand[row * CAND_CAP + i];
                const float* cp = cbf + (size_t)c * 256 + lane * 8;
                float d = 0.f;
                #pragma unroll
                for (int e = 0; e < 8; e++) d = fmaf(rr[e], __ldg(cp + e), d);
                #pragma unroll
                for (int off = 16; off > 0; off >>= 1) d += __shfl_xor_sync(0xffffffff, d, off);
                float s = __ldg(cn + c) - d;
                if (s < bv || (s == bv && c < bc)) { bv = s; bc = c; }
            }
        } else {
            for (int c = 0; c < 1024; c++) {
                const float* cp = cbf + (size_t)c * 256 + lane * 8;
                float d = 0.f;
                #pragma unroll
                for (int e = 0; e < 8; e++) d = fmaf(rr[e], __ldg(cp + e), d);
                #pragma unroll
                for (int off = 16; off > 0; off >>= 1) d += __shfl_xor_sync(0xffffffff, d, off);
                float s = __ldg(cn + c) - d;
                if (s < bv || (s == bv && c < bc)) { bv = s; bc = c; }
            }
        }
        if (lane == 0) {
            chosen[row] = bc;
            codes_out[(row0 + row) * 2 + Q] = (float)bc;
        }
    }
    __syncthreads();

    // update: residual / qbf / commitment loss (exact fp32)
    float vac = 0.f;
    #pragma unroll
    for (int i = 0; i < 32; i++) {
        int e = tid + 256 * i;
        int r = e >> 6, c4 = e & 63;
        int c = chosen[r];
        size_t off = (row0 + r) * 256 + 4 * c4;
        float4 cvv = *(const float4*)(cbf + (size_t)c * 256 + 4 * c4);
        float4 zv  = *(const float4*)(rg + off);
        float4 dv = make_float4(zv.x - cvv.x, zv.y - cvv.y, zv.z - cvv.z, zv.w - cvv.w);
        vac += dv.x * dv.x + dv.y * dv.y + dv.z * dv.z + dv.w * dv.w;
        if (Q == 0) {
            *(float4*)(res_out + off) = dv;
        } else {
            int c0 = ch0[r];
            float4 q0v = *(const float4*)(cbf0 + (size_t)c0 * 256 + 4 * c4);
            float4 sv = make_float4(q0v.x + cvv.x, q0v.y + cvv.y, q0v.z + cvv.z, q0v.w + cvv.w);
            __nv_bfloat162 h0; h0.x = __float2bfloat16(sv.x); h0.y = __float2bfloat16(sv.y);
            __nv_bfloat162 h1; h1.x = __float2bfloat16(sv.z); h1.y = __float2bfloat16(sv.w);
            *(__nv_bfloat162*)(qbf + off) = h0;
            *(__nv_bfloat162*)(qbf + off + 2) = h1;
        }
    }
    red[tid] = vac;
    __syncthreads();
    #pragma unroll
    for (int off = 128; off > 0; off >>= 1) {
        if (tid < off) red[tid] += red[tid + off];
        __syncthreads();
    }
    if (tid == 0) {
        if (Q == 0) vqpart[blockIdx.x] = red[0];
        else        vqpart[blockIdx.x] += red[0];
    }
}

// ================= final deterministic loss combine =================
__global__ __launch_bounds__(256) void final_k(
    const float* __restrict__ l1p, const float* __restrict__ vqp, float* __restrict__ out)
{
    __shared__ float sa[256], sb[256];
    float a = 0.f, b = 0.f;
    for (int i = threadIdx.x; i < RB128; i += 256) { a += l1p[i]; b += vqp[i]; }
    sa[threadIdx.x] = a; sb[threadIdx.x] = b;
    __syncthreads();
    #pragma unroll
    for (int off = 128; off > 0; off >>= 1) {
        if (threadIdx.x < off) {
            sa[threadIdx.x] += sa[threadIdx.x + off];
            sb[threadIdx.x] += sb[threadIdx.x + off];
        }
        __syncthreads();
    }
    if (threadIdx.x == 0) {
        float enc_loss = sa[0] / (131072.0f * 56.0f);
        float vq_loss  = sb[0] / (131072.0f * 256.0f);
        out[0] = enc_loss + 5.0f * vq_loss;
    }
}

// ================= launch =================
extern "C" void kernel_launch(void* const* d_in, const int* in_sizes, int n_in,
                              void* d_out, int out_size)
{
    const float* state = (const float*)d_in[0];
    const float* ew1 = (const float*)d_in[1];
    const float* eb1 = (const float*)d_in[2];
    const float* ew2 = (const float*)d_in[3];
    const float* eb2 = (const float*)d_in[4];
    const float* ew3 = (const float*)d_in[5];
    const float* eb3 = (const float*)d_in[6];
    const float* dw1 = (const float*)d_in[7];
    const float* db1 = (const float*)d_in[8];
    const float* dw2 = (const float*)d_in[9];
    const float* db2 = (const float*)d_in[10];
    const float* dw3 = (const float*)d_in[11];
    const float* db3 = (const float*)d_in[12];
    const float* cbk = (const float*)d_in[13];
    float* out = (float*)d_out;

    float *zb, *resb, *cnp, *l1p, *vqp;
    __nv_bfloat16 *qbf, *dbA, *dbB, *cbh, *wt1, *wt2, *wt3;
    __half *spin, *sp1, *sp2, *wsp1, *wsp2, *wsp3;
    cudaGetSymbolAddress((void**)&zb,   g_z);
    cudaGetSymbolAddress((void**)&resb, g_res);
    cudaGetSymbolAddress((void**)&qbf,  g_qbf);
    cudaGetSymbolAddress((void**)&dbA,  g_dbA);
    cudaGetSymbolAddress((void**)&dbB,  g_dbB);
    cudaGetSymbolAddress((void**)&spin, g_spin);
    cudaGetSymbolAddress((void**)&sp1,  g_sp1);
    cudaGetSymbolAddress((void**)&sp2,  g_sp2);
    cudaGetSymbolAddress((void**)&wsp1, g_wsp1);
    cudaGetSymbolAddress((void**)&wsp2, g_wsp2);
    cudaGetSymbolAddress((void**)&wsp3, g_wsp3);
    cudaGetSymbolAddress((void**)&cbh,  g_cbh);
    cudaGetSymbolAddress((void**)&wt1,  g_wt1);
    cudaGetSymbolAddress((void**)&wt2,  g_wt2);
    cudaGetSymbolAddress((void**)&wt3,  g_wt3);
    cudaGetSymbolAddress((void**)&cnp,  g_cn);
    cudaGetSymbolAddress((void**)&l1p,  g_l1p);
    cudaGetSymbolAddress((void**)&vqp,  g_vqp);

    const int DSM = 1024 + 3 * 32768;   // 99328
    cudaFuncSetAttribute(mgemm<64, 1, 1>,  cudaFuncAttributeMaxDynamicSharedMemorySize, DSM);
    cudaFuncSetAttribute(mgemm<512, 1, 1>, cudaFuncAttributeMaxDynamicSharedMemorySize, DSM);
    cudaFuncSetAttribute(mgemm<512, 1, 0>, cudaFuncAttributeMaxDynamicSharedMemorySize, DSM);
    cudaFuncSetAttribute(mgemm<256, 0, 2>, cudaFuncAttributeMaxDynamicSharedMemorySize, DSM);
    cudaFuncSetAttribute(mgemm<512, 0, 2>, cudaFuncAttributeMaxDynamicSharedMemorySize, DSM);
    cudaFuncSetAttribute(mgemm<512, 0, 3>, cudaFuncAttributeMaxDynamicSharedMemorySize, DSM);
    cudaFuncSetAttribute(vqscore_k<0>, cudaFuncAttributeMaxDynamicSharedMemorySize, VQ_SMEM);
    cudaFuncSetAttribute(vqscore_k<1>, cudaFuncAttributeMaxDynamicSharedMemorySize, VQ_SMEM);

    dim3 blk(256);

    // fused prep (9 ops, 1 launch)
    prep_k<<<PREP_BLOCKS, blk>>>(state, ew1, ew2, ew3, dw1, dw2, dw3, cbk,
                                 spin, wsp1, wsp2, wsp3, wt1, wt2, wt3, cbh, cnp);

    // encoder: fp16 split2 (3 plane-pairs, ~22-bit mantissa fidelity)
    mgemm<64, 1, 1><<<dim3(RB128, 4), blk, DSM>>>(spin, wsp1, eb1, sp1, 512, 512, nullptr, nullptr);
    mgemm<512, 1, 1><<<dim3(RB128, 4), blk, DSM>>>(sp1, wsp2, eb2, sp2, 512, 512, nullptr, nullptr);
    mgemm<512, 1, 0><<<dim3(RB128, 2), blk, DSM>>>(sp2, wsp3, eb3, zb, 256, 0, nullptr, nullptr);

    // residual VQ (ldmatrix bf16 scoring + exact fp32 re-argmin)
    vqscore_k<0><<<RB128, blk, VQ_SMEM>>>(zb, cbh, cbk, cbk, cnp,
                                          out + 1, resb, nullptr, vqp);
    vqscore_k<1><<<RB128, blk, VQ_SMEM>>>(resb, cbh + 1024*256, cbk + 1024*256, cbk, cnp + 1024,
                                          out + 1, nullptr, qbf, vqp);

    // decoder (bf16; only affects the scalar mean)
    mgemm<256, 0, 2><<<dim3(RB128, 4), blk, DSM>>>(qbf, wt1, db1, dbA, 512, 0, nullptr, nullptr);
    mgemm<512, 0, 2><<<dim3(RB128, 4), blk, DSM>>>(dbA, wt2, db2, dbB, 512, 0, nullptr, nullptr);
    mgemm<512, 0, 3><<<dim3(RB128, 1), blk, DSM>>>(dbB, wt3, db3, nullptr, 56, 0, state, l1p);

    final_k<<<1, 256>>>(l1p, vqp, out);
}

// round 9
// speedup vs baseline: 2.3677x; 1.0154x over previous
#include <cuda_runtime.h>
#include <cuda_bf16.h>
#include <cuda_fp16.h>
#include <math.h>

#define NROWS 131072
#define RB128 (NROWS/128)   // 1024
#define MARGIN 1.0f
#define CAND_CAP 32

// ---------------- scratch (device globals; no allocation allowed) ----------------
__device__ float g_z   [(size_t)NROWS * 256];
__device__ __nv_bfloat16 g_qbf [(size_t)NROWS * 256];
__device__ __nv_bfloat16 g_dbA [(size_t)NROWS * 512];
__device__ __nv_bfloat16 g_dbB [(size_t)NROWS * 512];
__device__ __half g_spin[(size_t)NROWS * 128];    // state split2 fp16, Kp=64
__device__ __half g_sp1 [(size_t)NROWS * 1024];   // h1 split2, Kp=512
__device__ __half g_sp2 [(size_t)NROWS * 1024];   // h2 split2, Kp=512
__device__ __half g_wsp1[512 * 128];
__device__ __half g_wsp2[512 * 1024];
__device__ __half g_wsp3[256 * 1024];
__device__ __nv_bfloat16 g_wt1[512 * 256];
__device__ __nv_bfloat16 g_wt2[512 * 512];
__device__ __nv_bfloat16 g_wt3[56 * 512];
__device__ __nv_bfloat16 g_cbh[2 * 1024 * 256];
__device__ float g_cn  [2 * 1024];
__device__ float g_l1p [RB128];
__device__ float g_vqp [RB128];

// ---------------- helpers ----------------
__device__ __forceinline__ unsigned smaddr(const void* p) {
    return (unsigned)__cvta_generic_to_shared(p);
}
__device__ __forceinline__ void cpa16(unsigned dst, const void* src, int sz) {
    asm volatile("cp.async.cg.shared.global [%0], [%1], 16, %2;\n"
                 :: "r"(dst), "l"(src), "r"(sz));
}
#define CP_COMMIT asm volatile("cp.async.commit_group;\n")
template<int N> __device__ __forceinline__ void cp_wait() {
    asm volatile("cp.async.wait_group %0;\n" :: "n"(N));
}
__device__ __forceinline__ void mma_bf16(float* c, const unsigned* a, unsigned b0, unsigned b1) {
    asm volatile(
        "mma.sync.aligned.m16n8k16.row.col.f32.bf16.bf16.f32 "
        "{%0,%1,%2,%3}, {%4,%5,%6,%7}, {%8,%9}, {%0,%1,%2,%3};\n"
        : "+f"(c[0]), "+f"(c[1]), "+f"(c[2]), "+f"(c[3])
        : "r"(a[0]), "r"(a[1]), "r"(a[2]), "r"(a[3]), "r"(b0), "r"(b1));
}
__device__ __forceinline__ void mma_f16(float* c, const unsigned* a, unsigned b0, unsigned b1) {
    asm volatile(
        "mma.sync.aligned.m16n8k16.row.col.f32.f16.f16.f32 "
        "{%0,%1,%2,%3}, {%4,%5,%6,%7}, {%8,%9}, {%0,%1,%2,%3};\n"
        : "+f"(c[0]), "+f"(c[1]), "+f"(c[2]), "+f"(c[3])
        : "r"(a[0]), "r"(a[1]), "r"(a[2]), "r"(a[3]), "r"(b0), "r"(b1));
}
__device__ __forceinline__ void ldsm4(unsigned& r0, unsigned& r1, unsigned& r2, unsigned& r3,
                                      unsigned addr) {
    asm volatile("ldmatrix.sync.aligned.m8n8.x4.shared.b16 {%0,%1,%2,%3}, [%4];"
                 : "=r"(r0), "=r"(r1), "=r"(r2), "=r"(r3) : "r"(addr));
}
__device__ __forceinline__ unsigned fford(float f) {
    unsigned u = __float_as_uint(f);
    return (u & 0x80000000u) ? ~u : (u | 0x80000000u);
}
__device__ __forceinline__ float iford(unsigned u) {
    return __uint_as_float((u & 0x80000000u) ? (u ^ 0x80000000u) : ~u);
}
__device__ __forceinline__ void split2h(float v, __half& h0, __half& h1)
{
    h0 = __float2half_rn(v);
    float r = v - __half2float(h0);
    h1 = __float2half_rn(r);
}
#define SWZ(r, cb) ((unsigned)((r) * 128 + ((cb) ^ (((r) & 7) << 4))))

// ================= unified mma.sync GEMM engine (1 barrier per chunk) =================
template<int KP, int SPLIT, int OUT>
__global__ __launch_bounds__(256) void mgemm(
    const void* __restrict__ Av, const void* __restrict__ BTv,
    const float* __restrict__ bias, void* __restrict__ Cv, int M, int KpN,
    const float* __restrict__ Xref, float* __restrict__ part)
{
    constexpr int NKC = KP / 64;
    constexpr int NCH = SPLIT ? 3 * NKC : NKC;
    constexpr int LDA = SPLIT ? 2 * KP : KP;
    const unsigned short* A  = (const unsigned short*)Av;
    const unsigned short* BT = (const unsigned short*)BTv;

    extern __shared__ __align__(16) char dynsm[];
    __shared__ float s_red[256];

    const int tid = threadIdx.x;
    const int lane = tid & 31, wid = tid >> 5;
    const int wm = wid & 3, wn = wid >> 2;
    const int row0 = blockIdx.x * 128;
    const int col0 = blockIdx.y * 128;

    unsigned dynb = (smaddr(dynsm) + 1023u) & ~1023u;
    unsigned Ab[3], Bb[3];
    #pragma unroll
    for (int s = 0; s < 3; s++) { Ab[s] = dynb + s * 32768u; Bb[s] = Ab[s] + 16384u; }

    float acc[2][8][4];
    #pragma unroll
    for (int a = 0; a < 2; a++)
        #pragma unroll
        for (int b = 0; b < 8; b++)
            #pragma unroll
            for (int c = 0; c < 4; c++) acc[a][b][c] = 0.f;

    auto choff = [&](int c, int& aoff, int& boff) {
        if (!SPLIT) { aoff = boff = c * 64; }
        else {
            constexpr int PI[3] = {1, 0, 0};
            constexpr int PJ[3] = {0, 1, 0};
            int pr = c / NKC, kc = c - pr * NKC;
            aoff = PI[pr] * KP + kc * 64;
            boff = PJ[pr] * KP + kc * 64;
        }
    };
    auto fill = [&](int s, int c) {
        int aoff, boff; choff(c, aoff, boff);
        #pragma unroll
        for (int i = 0; i < 4; i++) {
            int ch = tid + 256 * i;
            int r = ch >> 3, g = ch & 7;
            cpa16(Ab[s] + SWZ(r, g * 16),
                  A + (size_t)(row0 + r) * LDA + aoff + g * 8, 16);
        }
        #pragma unroll
        for (int i = 0; i < 4; i++) {
            int ch = tid + 256 * i;
            int r = ch >> 3, g = ch & 7;
            int br = col0 + r;
            int ok = (br < M);
            const unsigned short* src = BT + (size_t)(ok ? br : 0) * LDA + boff + g * 8;
            cpa16(Bb[s] + SWZ(r, g * 16), src, ok ? 16 : 0);
        }
    };

    const int lrow = ((lane >> 3) & 1) * 8 + (lane & 7);
    const int lcb  = (lane >= 16) ? 16 : 0;

    fill(0, 0); CP_COMMIT;
    if (NCH > 1) { fill(1, 1); CP_COMMIT; }

    for (int c = 0; c < NCH; c++) {
        const int s = c % 3;
        if (c + 1 < NCH) cp_wait<1>(); else cp_wait<0>();
        __syncthreads();   // all warps done with stage (c-1)%3 == (c+2)%3; fill target safe
        if (c + 2 < NCH) { fill((c + 2) % 3, c + 2); CP_COMMIT; }

        const unsigned Aw = Ab[s], Bw = Bb[s];
        #pragma unroll
        for (int kk = 0; kk < 64; kk += 16) {
            unsigned a[2][4];
            #pragma unroll
            for (int mf = 0; mf < 2; mf++) {
                int r = wm * 32 + mf * 16 + lrow;
                ldsm4(a[mf][0], a[mf][1], a[mf][2], a[mf][3], Aw + SWZ(r, kk * 2 + lcb));
            }
            unsigned bq[4][4];
            #pragma unroll
            for (int h = 0; h < 4; h++) {
                int r = wn * 64 + h * 16 + lrow;
                ldsm4(bq[h][0], bq[h][1], bq[h][2], bq[h][3], Bw + SWZ(r, kk * 2 + lcb));
            }
            #pragma unroll
            for (int nf = 0; nf < 8; nf++) {
                int h = nf >> 1, o = nf & 1;
                if (SPLIT) {
                    mma_f16(acc[0][nf], a[0], bq[h][o], bq[h][o + 2]);
                    mma_f16(acc[1][nf], a[1], bq[h][o], bq[h][o + 2]);
                } else {
                    mma_bf16(acc[0][nf], a[0], bq[h][o], bq[h][o + 2]);
                    mma_bf16(acc[1][nf], a[1], bq[h][o], bq[h][o + 2]);
                }
            }
        }
    }

    const int g = lane >> 2, q2 = (lane & 3) * 2;
    if (OUT == 0) {
        float* C = (float*)Cv;
        #pragma unroll
        for (int mf = 0; mf < 2; mf++) {
            int r1 = row0 + wm * 32 + mf * 16 + g;
            #pragma unroll
            for (int nf = 0; nf < 8; nf++) {
                int cc = col0 + wn * 64 + nf * 8 + q2;
                float2 o0 = make_float2(acc[mf][nf][0] + bias[cc], acc[mf][nf][1] + bias[cc + 1]);
                float2 o1 = make_float2(acc[mf][nf][2] + bias[cc], acc[mf][nf][3] + bias[cc + 1]);
                *(float2*)(C + (size_t)r1 * M + cc) = o0;
                *(float2*)(C + (size_t)(r1 + 8) * M + cc) = o1;
            }
        }
    } else if (OUT == 1) {
        __half* C = (__half*)Cv;
        const size_t strd = 2 * (size_t)KpN;
        #pragma unroll
        for (int mf = 0; mf < 2; mf++) {
            int r1 = row0 + wm * 32 + mf * 16 + g;
            #pragma unroll
            for (int nf = 0; nf < 8; nf++) {
                int cc = col0 + wn * 64 + nf * 8 + q2;
                #pragma unroll
                for (int half = 0; half < 2; half++) {
                    int r = r1 + (half ? 8 : 0);
                    float v0 = fmaxf(acc[mf][nf][2 * half + 0] + bias[cc], 0.f);
                    float v1 = fmaxf(acc[mf][nf][2 * half + 1] + bias[cc + 1], 0.f);
                    __half a0, a1, b0, b1;
                    split2h(v0, a0, a1);
                    split2h(v1, b0, b1);
                    __half* base = C + (size_t)r * strd + cc;
                    __half2 p0; p0.x = a0; p0.y = b0;
                    __half2 p1; p1.x = a1; p1.y = b1;
                    *(__half2*)(base)       = p0;
                    *(__half2*)(base + KpN) = p1;
                }
            }
        }
    } else if (OUT == 2) {
        __nv_bfloat16* C = (__nv_bfloat16*)Cv;
        #pragma unroll
        for (int mf = 0; mf < 2; mf++) {
            int r1 = row0 + wm * 32 + mf * 16 + g;
            #pragma unroll
            for (int nf = 0; nf < 8; nf++) {
                int cc = col0 + wn * 64 + nf * 8 + q2;
                float v0 = fmaxf(acc[mf][nf][0] + bias[cc], 0.f);
                float v1 = fmaxf(acc[mf][nf][1] + bias[cc + 1], 0.f);
                float v2 = fmaxf(acc[mf][nf][2] + bias[cc], 0.f);
                float v3 = fmaxf(acc[mf][nf][3] + bias[cc + 1], 0.f);
                __nv_bfloat162 h0; h0.x = __float2bfloat16(v0); h0.y = __float2bfloat16(v1);
                __nv_bfloat162 h1; h1.x = __float2bfloat16(v2); h1.y = __float2bfloat16(v3);
                *(__nv_bfloat162*)(C + (size_t)r1 * M + cc) = h0;
                *(__nv_bfloat162*)(C + (size_t)(r1 + 8) * M + cc) = h1;
            }
        }
    } else {
        float s = 0.f;
        #pragma unroll
        for (int mf = 0; mf < 2; mf++) {
            int r1 = row0 + wm * 32 + mf * 16 + g;
            #pragma unroll
            for (int nf = 0; nf < 8; nf++) {
                int cc = col0 + wn * 64 + nf * 8 + q2;
                #pragma unroll
                for (int e = 0; e < 4; e++) {
                    int c = cc + (e & 1);
                    int r = r1 + (e >= 2 ? 8 : 0);
                    if (c < M) {
                        float v = acc[mf][nf][e] + bias[c];
                        s += fabsf(Xref[(size_t)r * M + c] - v);
                    }
                }
            }
        }
        __syncthreads();
        s_red[tid] = s;
        __syncthreads();
        #pragma unroll
        for (int off = 128; off > 0; off >>= 1) {
            if (tid < off) s_red[tid] += s_red[tid + off];
            __syncthreads();
        }
        if (tid == 0) part[blockIdx.x] = s_red[0];
    }
}

// ================= fused prep kernel (unchanged from round 8) =================
__global__ __launch_bounds__(256) void prep_k(
    const float* __restrict__ state,
    const float* __restrict__ ew1, const float* __restrict__ ew2, const float* __restrict__ ew3,
    const float* __restrict__ dw1, const float* __restrict__ dw2, const float* __restrict__ dw3,
    const float* __restrict__ cbk,
    __half* __restrict__ spin, __half* __restrict__ wsp1, __half* __restrict__ wsp2,
    __half* __restrict__ wsp3,
    __nv_bfloat16* __restrict__ wt1, __nv_bfloat16* __restrict__ wt2,
    __nv_bfloat16* __restrict__ wt3, __nv_bfloat16* __restrict__ cbh,
    float* __restrict__ cnp)
{
    long gid = (long)blockIdx.x * 256 + threadIdx.x;

    if (gid < 8388608L) {
        long n = gid >> 6; int k = (int)(gid & 63);
        float v = (k < 56) ? state[n * 56 + k] : 0.f;
        __half h0, h1; split2h(v, h0, h1);
        __half* d = spin + n * 128;
        d[k] = h0; d[64 + k] = h1;
        return;
    }
    gid -= 8388608L;
    if (gid < 524288) { cbh[gid] = __float2bfloat16(cbk[gid]); return; }
    gid -= 524288;
    if (gid < 131072) {
        int k = (int)(gid / 512), m = (int)(gid % 512);
        wt1[(size_t)m * 256 + k] = __float2bfloat16(dw1[gid]);
        return;
    }
    gid -= 131072;
    if (gid < 262144) {
        int k = (int)(gid / 512), m = (int)(gid % 512);
        wt2[(size_t)m * 512 + k] = __float2bfloat16(dw2[gid]);
        return;
    }
    gid -= 262144;
    if (gid < 28672) {
        int k = (int)(gid / 56), m = (int)(gid % 56);
        wt3[(size_t)m * 512 + k] = __float2bfloat16(dw3[gid]);
        return;
    }
    gid -= 28672;
    if (gid < 32768) {
        int m = (int)(gid / 64), k = (int)(gid % 64);
        float v = (k < 56) ? ew1[(size_t)k * 512 + m] : 0.f;
        __half h0, h1; split2h(v, h0, h1);
        __half* d = wsp1 + (size_t)m * 128;
        d[k] = h0; d[64 + k] = h1;
        return;
    }
    gid -= 32768;
    if (gid < 262144) {
        int m = (int)(gid / 512), k = (int)(gid % 512);
        float v = ew2[(size_t)k * 512 + m];
        __half h0, h1; split2h(v, h0, h1);
        __half* d = wsp2 + (size_t)m * 1024;
        d[k] = h0; d[512 + k] = h1;
        return;
    }
    gid -= 262144;
    if (gid < 131072) {
        int m = (int)(gid / 512), k = (int)(gid % 512);
        float v = ew3[(size_t)k * 256 + m];
        __half h0, h1; split2h(v, h0, h1);
        __half* d = wsp3 + (size_t)m * 1024;
        d[k] = h0; d[512 + k] = h1;
        return;
    }
    gid -= 131072;
    if (gid < 65536) {
        int w = (int)(gid >> 5);
        int lane = (int)(gid & 31);
        const float* c = cbk + (size_t)w * 256;
        float s = 0.f;
        #pragma unroll
        for (int k = lane; k < 256; k += 32) s = fmaf(c[k], c[k], s);
        #pragma unroll
        for (int off = 16; off > 0; off >>= 1) s += __shfl_xor_sync(0xffffffff, s, off);
        if (lane == 0) cnp[w] = 0.5f * s;
    }
}
#define PREP_THREADS (8388608L + 524288 + 131072 + 262144 + 28672 + 32768 + 262144 + 131072 + 65536)
#define PREP_BLOCKS  ((int)((PREP_THREADS + 255) / 256))

// ================= fused residual-VQ: both quantizers in one kernel =================
// smem (rel. to aligned base):
//   As 0..65536 | Bs 65536..196608 | cand 196608..212992 | rowmin 212992..213504
//   cnt 213504..214016 | ch0 214016..214528 | ch1 214528..215040 | red 215040..216064
//   s0  216064..216068
#define VQ_SMEM (216068 + 1024)

// one scoring pass (8 code tiles) — identical instruction sequence to round 8
__device__ __forceinline__ void vq_score8(
    unsigned AsB, unsigned BsB, char* smc,
    const __nv_bfloat16* __restrict__ cbh, const float* __restrict__ cn,
    int* cand, unsigned* rowmin, int* cnt,
    int tid, int lane, int wid, int wm, int wn, int g, int q2, int lrow, int lcb)
{
    #pragma unroll
    for (int i = 0; i < 16; i++) {
        int ch = tid + 256 * i;
        int r = ch >> 5, gg = ch & 31;
        cpa16(BsB + (unsigned)(gg >> 3) * 16384u + SWZ(r, (gg & 7) * 16),
              cbh + (size_t)r * 256 + gg * 8, 16);
    }
    CP_COMMIT;

    for (int t = 0; t < 8; t++) {
        if (t < 7) {
            unsigned stb = BsB + (unsigned)((t + 1) & 1) * 65536u;
            #pragma unroll
            for (int i = 0; i < 16; i++) {
                int ch = tid + 256 * i;
                int r = ch >> 5, gg = ch & 31;
                cpa16(stb + (unsigned)(gg >> 3) * 16384u + SWZ(r, (gg & 7) * 16),
                      cbh + (size_t)((t + 1) * 128 + r) * 256 + gg * 8, 16);
            }
            CP_COMMIT;
            cp_wait<1>();
        } else {
            cp_wait<0>();
        }
        __syncthreads();

        float acc[2][8][4];
        #pragma unroll
        for (int a = 0; a < 2; a++)
            #pragma unroll
            for (int b = 0; b < 8; b++)
                #pragma unroll
                for (int c = 0; c < 4; c++) acc[a][b][c] = 0.f;

        const unsigned Bst = BsB + (unsigned)(t & 1) * 65536u;
        #pragma unroll
        for (int kk = 0; kk < 256; kk += 16) {
            int kb = kk >> 6;
            int kloc = (kk & 63) * 2;
            unsigned a[2][4];
            #pragma unroll
            for (int mf = 0; mf < 2; mf++) {
                int r = wm * 32 + mf * 16 + lrow;
                ldsm4(a[mf][0], a[mf][1], a[mf][2], a[mf][3],
                      AsB + (unsigned)kb * 16384u + SWZ(r, kloc + lcb));
            }
            unsigned bq[4][4];
            #pragma unroll
            for (int h = 0; h < 4; h++) {
                int r = wn * 64 + h * 16 + lrow;
                ldsm4(bq[h][0], bq[h][1], bq[h][2], bq[h][3],
                      Bst + (unsigned)kb * 16384u + SWZ(r, kloc + lcb));
            }
            #pragma unroll
            for (int nf = 0; nf < 8; nf++) {
                int h = nf >> 1, o = nf & 1;
                mma_bf16(acc[0][nf], a[0], bq[h][o], bq[h][o + 2]);
                mma_bf16(acc[1][nf], a[1], bq[h][o], bq[h][o + 2]);
            }
        }

        #pragma unroll
        for (int mf = 0; mf < 2; mf++) {
            int r1 = wm * 32 + mf * 16 + g;
            float m1 = 1e30f, m2 = 1e30f;
            #pragma unroll
            for (int nf = 0; nf < 8; nf++) {
                int cl = wn * 64 + nf * 8 + q2;
                float cn0 = __ldg(cn + t * 128 + cl);
                float cn1 = __ldg(cn + t * 128 + cl + 1);
                float s0 = cn0 - acc[mf][nf][0];
                float s1 = cn1 - acc[mf][nf][1];
                float s2 = cn0 - acc[mf][nf][2];
                float s3 = cn1 - acc[mf][nf][3];
                acc[mf][nf][0] = s0; acc[mf][nf][1] = s1;
                acc[mf][nf][2] = s2; acc[mf][nf][3] = s3;
                m1 = fminf(m1, fminf(s0, s1));
                m2 = fminf(m2, fminf(s2, s3));
            }
            atomicMin(&rowmin[r1], fford(m1));
            atomicMin(&rowmin[r1 + 8], fford(m2));
        }
        __syncthreads();
        #pragma unroll
        for (int mf = 0; mf < 2; mf++) {
            int r1 = wm * 32 + mf * 16 + g;
            float thr1 = iford(rowmin[r1]) + MARGIN;
            float thr2 = iford(rowmin[r1 + 8]) + MARGIN;
            #pragma unroll
            for (int nf = 0; nf < 8; nf++) {
                int code = t * 128 + wn * 64 + nf * 8 + q2;
                #pragma unroll
                for (int e = 0; e < 4; e++) {
                    float s = acc[mf][nf][e];
                    int r = (e >= 2) ? (r1 + 8) : r1;
                    float thr = (e >= 2) ? thr2 : thr1;
                    if (s <= thr) {
                        int p = atomicAdd(&cnt[r], 1);
                        if (p < CAND_CAP) cand[r * CAND_CAP + p] = code + (e & 1);
                    }
                }
            }
        }
        __syncthreads();
    }
}

// exact-fp32 argmin over candidate list (or full scan on overflow)
__device__ __forceinline__ void vq_rescue(
    const float rr[8], const float* __restrict__ cbf, const float* __restrict__ cn,
    const int* cand, int row, int cv, int lane, int& bc_out)
{
    float bv = 1e30f; int bc = 0;
    if (cv <= CAND_CAP) {
        for (int i = 0; i < cv; i++) {
            int c = cand[row * CAND_CAP + i];
            const float* cp = cbf + (size_t)c * 256 + lane * 8;
            float d = 0.f;
            #pragma unroll
            for (int e = 0; e < 8; e++) d = fmaf(rr[e], __ldg(cp + e), d);
            #pragma unroll
            for (int off = 16; off > 0; off >>= 1) d += __shfl_xor_sync(0xffffffff, d, off);
            float s = __ldg(cn + c) - d;
            if (s < bv || (s == bv && c < bc)) { bv = s; bc = c; }
        }
    } else {
        for (int c = 0; c < 1024; c++) {
            const float* cp = cbf + (size_t)c * 256 + lane * 8;
            float d = 0.f;
            #pragma unroll
            for (int e = 0; e < 8; e++) d = fmaf(rr[e], __ldg(cp + e), d);
            #pragma unroll
            for (int off = 16; off > 0; off >>= 1) d += __shfl_xor_sync(0xffffffff, d, off);
            float s = __ldg(cn + c) - d;
            if (s < bv || (s == bv && c < bc)) { bv = s; bc = c; }
        }
    }
    bc_out = bc;
}

__global__ __launch_bounds__(256) void vqfused_k(
    const float* __restrict__ zg, const __nv_bfloat16* __restrict__ cbh,
    const float* __restrict__ cbf, const float* __restrict__ cn,
    float* __restrict__ codes_out, __nv_bfloat16* __restrict__ qbf,
    float* __restrict__ vqpart)
{
    extern __shared__ __align__(16) char sm[];
    unsigned dynb = (smaddr(sm) + 1023u) & ~1023u;
    char* smc = sm + (int)(dynb - smaddr(sm));
    const unsigned AsB = dynb;
    const unsigned BsB = dynb + 65536u;
    int*      cand   = (int*)     (smc + 196608);
    unsigned* rowmin = (unsigned*)(smc + 212992);
    int*      cnt    = (int*)     (smc + 213504);
    int*      ch0    = (int*)     (smc + 214016);
    int*      ch1    = (int*)     (smc + 214528);
    float*    red    = (float*)   (smc + 215040);
    float*    s0p    = (float*)   (smc + 216064);

    const int tid = threadIdx.x;
    const int lane = tid & 31, wid = tid >> 5;
    const int wm = wid & 3, wn = wid >> 2;
    const size_t row0 = (size_t)blockIdx.x * 128;
    const int g = lane >> 2, q2 = (lane & 3) * 2;
    const int lrow = ((lane >> 3) & 1) * 8 + (lane & 7);
    const int lcb  = (lane >= 16) ? 16 : 0;

    const __nv_bfloat16* cbh1 = cbh + 1024 * 256;
    const float* cbf1 = cbf + 1024 * 256;
    const float* cn1  = cn + 1024;

    if (tid < 128) { rowmin[tid] = 0xFFFFFFFFu; cnt[tid] = 0; }

    // ---- phase 0: A tile = bf16(z), swizzled ----
    #pragma unroll
    for (int i = 0; i < 32; i++) {
        int e = tid + 256 * i;
        int r = e >> 6, c4 = e & 63;
        float4 v = *(const float4*)(zg + (row0 + r) * 256 + 4 * c4);
        __nv_bfloat162 h0; h0.x = __float2bfloat16(v.x); h0.y = __float2bfloat16(v.y);
        __nv_bfloat162 h1; h1.x = __float2bfloat16(v.z); h1.y = __float2bfloat16(v.w);
        uint2 p; p.x = *(unsigned*)&h0; p.y = *(unsigned*)&h1;
        int kb = c4 >> 4;
        unsigned off = (unsigned)kb * 16384u + (unsigned)r * 128u
                     + (((unsigned)((c4 * 8) & 127)) ^ (((unsigned)r & 7u) << 4));
        *(uint2*)(smc + off) = p;
    }
    __syncthreads();

    vq_score8(AsB, BsB, smc, cbh, cn, cand, rowmin, cnt,
              tid, lane, wid, wm, wn, g, q2, lrow, lcb);

    // rescue Q0 (rr = z row)
    for (int j = 0; j < 16; j++) {
        int row = wid + 8 * j;
        const float* rp = zg + (row0 + row) * 256 + lane * 8;
        float4 u = *(const float4*)rp;
        float4 v = *(const float4*)(rp + 4);
        float rr[8] = {u.x, u.y, u.z, u.w, v.x, v.y, v.z, v.w};
        int bc;
        vq_rescue(rr, cbf, cn, cand, row, cnt[row], lane, bc);
        if (lane == 0) {
            ch0[row] = bc;
            codes_out[(row0 + row) * 2 + 0] = (float)bc;
        }
    }
    __syncthreads();

    // ---- update 0: residual -> bf16 As (in place), commitment partial ----
    float vac = 0.f;
    #pragma unroll
    for (int i = 0; i < 32; i++) {
        int e = tid + 256 * i;
        int r = e >> 6, c4 = e & 63;
        int c = ch0[r];
        size_t off = (row0 + r) * 256 + 4 * c4;
        float4 cvv = *(const float4*)(cbf + (size_t)c * 256 + 4 * c4);
        float4 zv  = *(const float4*)(zg + off);
        float4 dv = make_float4(zv.x - cvv.x, zv.y - cvv.y, zv.z - cvv.z, zv.w - cvv.w);
        vac += dv.x * dv.x + dv.y * dv.y + dv.z * dv.z + dv.w * dv.w;
        __nv_bfloat162 h0; h0.x = __float2bfloat16(dv.x); h0.y = __float2bfloat16(dv.y);
        __nv_bfloat162 h1; h1.x = __float2bfloat16(dv.z); h1.y = __float2bfloat16(dv.w);
        uint2 p; p.x = *(unsigned*)&h0; p.y = *(unsigned*)&h1;
        int kb = c4 >> 4;
        unsigned soff = (unsigned)kb * 16384u + (unsigned)r * 128u
                      + (((unsigned)((c4 * 8) & 127)) ^ (((unsigned)r & 7u) << 4));
        *(uint2*)(smc + soff) = p;
    }
    red[tid] = vac;
    __syncthreads();
    #pragma unroll
    for (int off = 128; off > 0; off >>= 1) {
        if (tid < off) red[tid] += red[tid + off];
        __syncthreads();
    }
    if (tid == 0) *s0p = red[0];
    if (tid < 128) { rowmin[tid] = 0xFFFFFFFFu; cnt[tid] = 0; }
    __syncthreads();

    // ---- phase 1: score vs codebook 1 ----
    vq_score8(AsB, BsB, smc, cbh1, cn1, cand, rowmin, cnt,
              tid, lane, wid, wm, wn, g, q2, lrow, lcb);

    // rescue Q1 (rr = z - cb0[ch0], bitwise == old res buffer)
    for (int j = 0; j < 16; j++) {
        int row = wid + 8 * j;
        const float* rp = zg + (row0 + row) * 256 + lane * 8;
        const float* cp0 = cbf + (size_t)ch0[row] * 256 + lane * 8;
        float4 u = *(const float4*)rp;
        float4 v = *(const float4*)(rp + 4);
        float4 a = *(const float4*)cp0;
        float4 b = *(const float4*)(cp0 + 4);
        float rr[8] = {u.x - a.x, u.y - a.y, u.z - a.z, u.w - a.w,
                       v.x - b.x, v.y - b.y, v.z - b.z, v.w - b.w};
        int bc;
        vq_rescue(rr, cbf1, cn1, cand, row, cnt[row], lane, bc);
        if (lane == 0) {
            ch1[row] = bc;
            codes_out[(row0 + row) * 2 + 1] = (float)bc;
        }
    }
    __syncthreads();

    // ---- update 1: commitment partial + qbf = bf16(cb0 + cb1) ----
    vac = 0.f;
    #pragma unroll
    for (int i = 0; i < 32; i++) {
        int e = tid + 256 * i;
        int r = e >> 6, c4 = e & 63;
        int c = ch1[r], c0 = ch0[r];
        size_t off = (row0 + r) * 256 + 4 * c4;
        float4 cvv = *(const float4*)(cbf1 + (size_t)c * 256 + 4 * c4);
        float4 q0v = *(const float4*)(cbf + (size_t)c0 * 256 + 4 * c4);
        float4 zv  = *(const float4*)(zg + off);
        float4 rv = make_float4(zv.x - q0v.x, zv.y - q0v.y, zv.z - q0v.z, zv.w - q0v.w);
        float4 dv = make_float4(rv.x - cvv.x, rv.y - cvv.y, rv.z - cvv.z, rv.w - cvv.w);
        vac += dv.x * dv.x + dv.y * dv.y + dv.z * dv.z + dv.w * dv.w;
        float4 sv = make_float4(q0v.x + cvv.x, q0v.y + cvv.y, q0v.z + cvv.z, q0v.w + cvv.w);
        __nv_bfloat162 h0; h0.x = __float2bfloat16(sv.x); h0.y = __float2bfloat16(sv.y);
        __nv_bfloat162 h1; h1.x = __float2bfloat16(sv.z); h1.y = __float2bfloat16(sv.w);
        *(__nv_bfloat162*)(qbf + off) = h0;
        *(__nv_bfloat162*)(qbf + off + 2) = h1;
    }
    red[tid] = vac;
    __syncthreads();
    #pragma unroll
    for (int off = 128; off > 0; off >>= 1) {
        if (tid < off) red[tid] += red[tid + off];
        __syncthreads();
    }
    if (tid == 0) vqpart[blockIdx.x] = *s0p + red[0];
}

// ================= final deterministic loss combine =================
__global__ __launch_bounds__(256) void final_k(
    const float* __restrict__ l1p, const float* __restrict__ vqp, float* __restrict__ out)
{
    __shared__ float sa[256], sb[256];
    float a = 0.f, b = 0.f;
    for (int i = threadIdx.x; i < RB128; i += 256) { a += l1p[i]; b += vqp[i]; }
    sa[threadIdx.x] = a; sb[threadIdx.x] = b;
    __syncthreads();
    #pragma unroll
    for (int off = 128; off > 0; off >>= 1) {
        if (threadIdx.x < off) {
            sa[threadIdx.x] += sa[threadIdx.x + off];
            sb[threadIdx.x] += sb[threadIdx.x + off];
        }
        __syncthreads();
    }
    if (threadIdx.x == 0) {
        float enc_loss = sa[0] / (131072.0f * 56.0f);
        float vq_loss  = sb[0] / (131072.0f * 256.0f);
        out[0] = enc_loss + 5.0f * vq_loss;
    }
}

// ================= launch =================
extern "C" void kernel_launch(void* const* d_in, const int* in_sizes, int n_in,
                              void* d_out, int out_size)
{
    const float* state = (const float*)d_in[0];
    const float* ew1 = (const float*)d_in[1];
    const float* eb1 = (const float*)d_in[2];
    const float* ew2 = (const float*)d_in[3];
    const float* eb2 = (const float*)d_in[4];
    const float* ew3 = (const float*)d_in[5];
    const float* eb3 = (const float*)d_in[6];
    const float* dw1 = (const float*)d_in[7];
    const float* db1 = (const float*)d_in[8];
    const float* dw2 = (const float*)d_in[9];
    const float* db2 = (const float*)d_in[10];
    const float* dw3 = (const float*)d_in[11];
    const float* db3 = (const float*)d_in[12];
    const float* cbk = (const float*)d_in[13];
    float* out = (float*)d_out;

    float *zb, *cnp, *l1p, *vqp;
    __nv_bfloat16 *qbf, *dbA, *dbB, *cbh, *wt1, *wt2, *wt3;
    __half *spin, *sp1, *sp2, *wsp1, *wsp2, *wsp3;
    cudaGetSymbolAddress((void**)&zb,   g_z);
    cudaGetSymbolAddress((void**)&qbf,  g_qbf);
    cudaGetSymbolAddress((void**)&dbA,  g_dbA);
    cudaGetSymbolAddress((void**)&dbB,  g_dbB);
    cudaGetSymbolAddress((void**)&spin, g_spin);
    cudaGetSymbolAddress((void**)&sp1,  g_sp1);
    cudaGetSymbolAddress((void**)&sp2,  g_sp2);
    cudaGetSymbolAddress((void**)&wsp1, g_wsp1);
    cudaGetSymbolAddress((void**)&wsp2, g_wsp2);
    cudaGetSymbolAddress((void**)&wsp3, g_wsp3);
    cudaGetSymbolAddress((void**)&cbh,  g_cbh);
    cudaGetSymbolAddress((void**)&wt1,  g_wt1);
    cudaGetSymbolAddress((void**)&wt2,  g_wt2);
    cudaGetSymbolAddress((void**)&wt3,  g_wt3);
    cudaGetSymbolAddress((void**)&cnp,  g_cn);
    cudaGetSymbolAddress((void**)&l1p,  g_l1p);
    cudaGetSymbolAddress((void**)&vqp,  g_vqp);

    const int DSM = 1024 + 3 * 32768;   // 99328
    cudaFuncSetAttribute(mgemm<64, 1, 1>,  cudaFuncAttributeMaxDynamicSharedMemorySize, DSM);
    cudaFuncSetAttribute(mgemm<512, 1, 1>, cudaFuncAttributeMaxDynamicSharedMemorySize, DSM);
    cudaFuncSetAttribute(mgemm<512, 1, 0>, cudaFuncAttributeMaxDynamicSharedMemorySize, DSM);
    cudaFuncSetAttribute(mgemm<256, 0, 2>, cudaFuncAttributeMaxDynamicSharedMemorySize, DSM);
    cudaFuncSetAttribute(mgemm<512, 0, 2>, cudaFuncAttributeMaxDynamicSharedMemorySize, DSM);
    cudaFuncSetAttribute(mgemm<512, 0, 3>, cudaFuncAttributeMaxDynamicSharedMemorySize, DSM);
    cudaFuncSetAttribute(vqfused_k, cudaFuncAttributeMaxDynamicSharedMemorySize, VQ_SMEM);

    dim3 blk(256);

    // fused prep (9 ops, 1 launch)
    prep_k<<<PREP_BLOCKS, blk>>>(state, ew1, ew2, ew3, dw1, dw2, dw3, cbk,
                                 spin, wsp1, wsp2, wsp3, wt1, wt2, wt3, cbh, cnp);

    // encoder: fp16 split2 (3 plane-pairs, ~22-bit mantissa fidelity)
    mgemm<64, 1, 1><<<dim3(RB128, 4), blk, DSM>>>(spin, wsp1, eb1, sp1, 512, 512, nullptr, nullptr);
    mgemm<512, 1, 1><<<dim3(RB128, 4), blk, DSM>>>(sp1, wsp2, eb2, sp2, 512, 512, nullptr, nullptr);
    mgemm<512, 1, 0><<<dim3(RB128, 2), blk, DSM>>>(sp2, wsp3, eb3, zb, 256, 0, nullptr, nullptr);

    // fused residual VQ (both quantizers, no residual round-trip)
    vqfused_k<<<RB128, blk, VQ_SMEM>>>(zb, cbh, cbk, cnp, out + 1, qbf, vqp);

    // decoder (bf16; only affects the scalar mean)
    mgemm<256, 0, 2><<<dim3(RB128, 4), blk, DSM>>>(qbf, wt1, db1, dbA, 512, 0, nullptr, nullptr);
    mgemm<512, 0, 2><<<dim3(RB128, 4), blk, DSM>>>(dbA, wt2, db2, dbB, 512, 0, nullptr, nullptr);
    mgemm<512, 0, 3><<<dim3(RB128, 1), blk, DSM>>>(dbB, wt3, db3, nullptr, 56, 0, state, l1p);

    final_k<<<1, 256>>>(l1p, vqp, out);
}